// round 6
// baseline (speedup 1.0000x reference)
#include <cuda_runtime.h>
#include <math_constants.h>
#include <stdint.h>

// Problem constants (shapes fixed by the reference).
#define MAX_N 100032
#define MAX_E 1600000
#define D_IN  128
#define D_OUT 64

// ---------------- Scratch (static __device__ globals; no runtime allocs) ---
__device__ int g_flag;                    // 1 => edge_index is int64, 0 => int32
__device__ int g_src[MAX_E];
__device__ int g_dst[MAX_E];
__device__ int g_csr[MAX_E];              // src indices grouped by dst
__device__ int g_deg[MAX_N];
__device__ int g_off[MAX_N + 1];
__device__ int g_cur[MAX_N];
__device__ int g_bsum[128];

// ---------------- K0: detect edge_index dtype + zero histogram -------------
// If int64 (little-endian), all odd 32-bit words of in-range indices are 0.
__global__ void k_detect_zero(const unsigned int* __restrict__ w, int n) {
    int i = blockIdx.x * blockDim.x + threadIdx.x;
    if (i < n) g_deg[i] = 0;
    if (blockIdx.x == 0 && threadIdx.x < 32) {
        unsigned int v = 0;
        for (int j = threadIdx.x * 2 + 1; j < 512; j += 64) v |= w[j];
        v = __reduce_or_sync(0xffffffffu, v);
        if (threadIdx.x == 0) g_flag = (v == 0u) ? 1 : 0;
    }
}

// ---------------- K1: normalize edges to int32 + histogram -----------------
__global__ void k_count(const void* __restrict__ ei, int E) {
    int e = blockIdx.x * blockDim.x + threadIdx.x;
    if (e >= E) return;
    int s, d;
    if (g_flag) {
        const long long* p = (const long long*)ei;
        s = (int)p[e];
        d = (int)p[(size_t)E + e];
    } else {
        const int* p = (const int*)ei;
        s = p[e];
        d = p[E + e];
    }
    g_src[e] = s;
    g_dst[e] = d;
    atomicAdd(&g_deg[d], 1);
}

// ---------------- K2a: per-block exclusive scan (1024 elems/block) ---------
__global__ __launch_bounds__(1024) void k_scan1(int n) {
    __shared__ int wsum[32];
    int t = threadIdx.x;
    int i = blockIdx.x * 1024 + t;
    int lane = t & 31;
    int wid = t >> 5;

    int d = (i < n) ? g_deg[i] : 0;
    int inc = d;
#pragma unroll
    for (int o = 1; o < 32; o <<= 1) {
        int v = __shfl_up_sync(0xffffffffu, inc, o);
        if (lane >= o) inc += v;
    }
    if (lane == 31) wsum[wid] = inc;
    __syncthreads();
    if (wid == 0) {
        int s = wsum[lane];
        int si = s;
#pragma unroll
        for (int o = 1; o < 32; o <<= 1) {
            int v = __shfl_up_sync(0xffffffffu, si, o);
            if (lane >= o) si += v;
        }
        wsum[lane] = si - s;   // exclusive warp prefix
        if (lane == 31 && blockIdx.x < 128) g_bsum[blockIdx.x] = si;
    }
    __syncthreads();
    if (i < n) g_off[i] = inc - d + wsum[wid];   // block-local exclusive
}

// ---------------- K2b: add global block offsets (redundant local scan) -----
// Each block independently prefix-sums the <=98 block sums in smem (cheap),
// then applies. Replaces the separate single-block scan kernel.
__global__ void k_scan23(int n, int E, int nb) {
    __shared__ int pre[128];
    int t = threadIdx.x;
    if (t < 128) {
        int s = 0;
        for (int k = 0; k < t && k < nb; k++) s += g_bsum[k];
        pre[t] = s;
    }
    __syncthreads();
    int i = blockIdx.x * blockDim.x + t;
    if (i < n) {
        int off = g_off[i] + pre[i >> 10];
        g_off[i] = off;
        g_cur[i] = off;
    }
    if (i == 0) g_off[n] = E;
}

// ---------------- K3: scatter src into CSR buckets -------------------------
__global__ void k_scatter(int E) {
    int e = blockIdx.x * blockDim.x + threadIdx.x;
    if (e >= E) return;
    int d = g_dst[e];
    int pos = atomicAdd(&g_cur[d], 1);
    g_csr[pos] = g_src[e];
}

// ---------------- K4: fused gather-max + GEMM + bias + log_softmax ---------
// Per block: 64 nodes, 128 threads.
// Phase 1: 4 warps gather-max neighborhoods (16 nodes/warp) into smem
//          As_agg[k][node] (k-major, pad 65).
// Phase 2: 64x64 GEMM over K=256 ([agg | x] @ [Wl | Wr]^T), 4 nodes x 8 outs
//          per thread; agg half read from smem, x half staged into consumed
//          As_agg rows. Then bias + per-node log_softmax.
__global__ __launch_bounds__(128) void k_aggemm(const float* __restrict__ x,
                                                const float* __restrict__ Wl,
                                                const float* __restrict__ bl,
                                                const float* __restrict__ Wr,
                                                float* __restrict__ out, int N) {
    __shared__ float As_agg[128][65];
    __shared__ float Bs[32][68];   // pad 68 keeps float4 rows 16B-aligned

    int t = threadIdx.x;
    int w = t >> 5;
    int lane = t & 31;
    int nb = blockIdx.x * 64;

    // ---------- Phase 1: gather-max into As_agg ----------
    const float4* xv = (const float4*)x;
#pragma unroll 1
    for (int r = 0; r < 16; r++) {
        int ln = w * 16 + r;
        int n = nb + ln;
        float4 acc = make_float4(0.f, 0.f, 0.f, 0.f);
        if (n < N) {
            int beg = g_off[n];
            int end = g_off[n + 1];
            if (beg < end) {
                acc = make_float4(-CUDART_INF_F, -CUDART_INF_F,
                                  -CUDART_INF_F, -CUDART_INF_F);
                int e = beg;
                for (; e + 3 < end; e += 4) {
                    int s0 = g_csr[e];
                    int s1 = g_csr[e + 1];
                    int s2 = g_csr[e + 2];
                    int s3 = g_csr[e + 3];
                    float4 v0 = xv[(size_t)s0 * 32 + lane];
                    float4 v1 = xv[(size_t)s1 * 32 + lane];
                    float4 v2 = xv[(size_t)s2 * 32 + lane];
                    float4 v3 = xv[(size_t)s3 * 32 + lane];
                    acc.x = fmaxf(acc.x, fmaxf(fmaxf(v0.x, v1.x), fmaxf(v2.x, v3.x)));
                    acc.y = fmaxf(acc.y, fmaxf(fmaxf(v0.y, v1.y), fmaxf(v2.y, v3.y)));
                    acc.z = fmaxf(acc.z, fmaxf(fmaxf(v0.z, v1.z), fmaxf(v2.z, v3.z)));
                    acc.w = fmaxf(acc.w, fmaxf(fmaxf(v0.w, v1.w), fmaxf(v2.w, v3.w)));
                }
                for (; e < end; e++) {
                    int s0 = g_csr[e];
                    float4 v0 = xv[(size_t)s0 * 32 + lane];
                    acc.x = fmaxf(acc.x, v0.x);
                    acc.y = fmaxf(acc.y, v0.y);
                    acc.z = fmaxf(acc.z, v0.z);
                    acc.w = fmaxf(acc.w, v0.w);
                }
            }
        }
        As_agg[lane * 4 + 0][ln] = acc.x;
        As_agg[lane * 4 + 1][ln] = acc.y;
        As_agg[lane * 4 + 2][ln] = acc.z;
        As_agg[lane * 4 + 3][ln] = acc.w;
    }
    __syncthreads();

    // ---------- Phase 2: GEMM ----------
    int tx = t & 7;       // output group (8 outs: tx*8..tx*8+7)
    int ty = t >> 3;      // node group (4 nodes: ty*4..ty*4+3)
    int kq = (t & 7) * 4; // staging k offset within chunk (0..28)
    int row = t >> 3;     // staging row 0..15

    float acc[4][8];
#pragma unroll
    for (int i = 0; i < 4; i++)
#pragma unroll
        for (int j = 0; j < 8; j++) acc[i][j] = 0.f;

    for (int kb = 0; kb < 256; kb += 32) {
        const float* Wsrc = (kb < 128) ? (Wl + kb) : (Wr + (kb - 128));

#pragma unroll
        for (int r2 = 0; r2 < 4; r2++) {
            int c = row + r2 * 16;   // 0..63
            float4 wv = *(const float4*)(Wsrc + (size_t)c * D_IN + kq);
            Bs[kq + 0][c] = wv.x;
            Bs[kq + 1][c] = wv.y;
            Bs[kq + 2][c] = wv.z;
            Bs[kq + 3][c] = wv.w;

            if (kb >= 128) {
                int n = nb + c;
                float4 v = (n < N)
                    ? *(const float4*)(x + (size_t)n * D_IN + (kb - 128) + kq)
                    : make_float4(0.f, 0.f, 0.f, 0.f);
                int kr = (kb - 128) + kq;
                As_agg[kr + 0][c] = v.x;
                As_agg[kr + 1][c] = v.y;
                As_agg[kr + 2][c] = v.z;
                As_agg[kr + 3][c] = v.w;
            }
        }
        __syncthreads();

        const float (*Arows)[65] = As_agg + (kb & 127);
#pragma unroll
        for (int kk = 0; kk < 32; kk++) {
            float a0 = Arows[kk][ty * 4 + 0];
            float a1 = Arows[kk][ty * 4 + 1];
            float a2 = Arows[kk][ty * 4 + 2];
            float a3 = Arows[kk][ty * 4 + 3];
            float4 blo = *(const float4*)&Bs[kk][tx * 8];
            float4 bhi = *(const float4*)&Bs[kk][tx * 8 + 4];
            float b[8] = {blo.x, blo.y, blo.z, blo.w, bhi.x, bhi.y, bhi.z, bhi.w};
#pragma unroll
            for (int j = 0; j < 8; j++) {
                acc[0][j] += a0 * b[j];
                acc[1][j] += a1 * b[j];
                acc[2][j] += a2 * b[j];
                acc[3][j] += a3 * b[j];
            }
        }
        __syncthreads();
    }

    // bias
    float bv[8];
#pragma unroll
    for (int j = 0; j < 8; j++) bv[j] = bl[tx * 8 + j];
#pragma unroll
    for (int i = 0; i < 4; i++)
#pragma unroll
        for (int j = 0; j < 8; j++) acc[i][j] += bv[j];

    // log_softmax per node row: node (nb + ty*4 + i)'s 64 outputs live in the
    // 8 lanes sharing this ty (tx = 0..7) -> shfl_xor 4,2,1 within the group.
#pragma unroll
    for (int i = 0; i < 4; i++) {
        float m = acc[i][0];
#pragma unroll
        for (int j = 1; j < 8; j++) m = fmaxf(m, acc[i][j]);
#pragma unroll
        for (int o = 4; o >= 1; o >>= 1)
            m = fmaxf(m, __shfl_xor_sync(0xffffffffu, m, o));
        float s = 0.f;
#pragma unroll
        for (int j = 0; j < 8; j++) s += expf(acc[i][j] - m);
#pragma unroll
        for (int o = 4; o >= 1; o >>= 1)
            s += __shfl_xor_sync(0xffffffffu, s, o);
        float lse = m + logf(s);

        int n = nb + ty * 4 + i;
        if (n < N) {
            float4 o0 = make_float4(acc[i][0] - lse, acc[i][1] - lse,
                                    acc[i][2] - lse, acc[i][3] - lse);
            float4 o1 = make_float4(acc[i][4] - lse, acc[i][5] - lse,
                                    acc[i][6] - lse, acc[i][7] - lse);
            *(float4*)(out + (size_t)n * D_OUT + tx * 8) = o0;
            *(float4*)(out + (size_t)n * D_OUT + tx * 8 + 4) = o1;
        }
    }
}

// ---------------- launcher -------------------------------------------------
extern "C" void kernel_launch(void* const* d_in, const int* in_sizes, int n_in,
                              void* d_out, int out_size) {
    const float* x  = (const float*)d_in[0];
    const void*  ei = d_in[1];
    const float* Wl = (const float*)d_in[2];
    const float* bl = (const float*)d_in[3];
    const float* Wr = (const float*)d_in[4];
    float* out = (float*)d_out;

    int N = in_sizes[0] / D_IN;
    int E = in_sizes[1] / 2;
    int nb = (N + 1023) / 1024;

    // Launch order matters for ncu (-s 5 -c 1): k_aggemm sits at index 5.
    k_detect_zero<<<(N + 255) / 256, 256>>>((const unsigned int*)ei, N);  // 0
    k_count<<<(E + 255) / 256, 256>>>(ei, E);                             // 1
    k_scan1<<<nb, 1024>>>(N);                                             // 2
    k_scan23<<<(N + 255) / 256, 256>>>(N, E, nb);                         // 3
    k_scatter<<<(E + 255) / 256, 256>>>(E);                               // 4
    k_aggemm<<<(N + 63) / 64, 128>>>(x, Wl, bl, Wr, out, N);              // 5
}

// round 7
// speedup vs baseline: 1.0305x; 1.0305x over previous
#include <cuda_runtime.h>
#include <math_constants.h>
#include <stdint.h>

// Problem constants (shapes fixed by the reference).
#define MAX_N 100032
#define MAX_E 1600000
#define D_IN  128
#define D_OUT 64

// ---------------- Scratch (static __device__ globals; no runtime allocs) ---
// g_deg is zero at module load; k_scatter re-zeroes it for the NEXT invocation
// (graph replays run the identical sequence, so the invariant holds).
__device__ int g_deg[MAX_N];
__device__ int g_off[MAX_N + 1];
__device__ int g_cur[MAX_N];
__device__ int g_csr[MAX_E];              // src indices grouped by dst

// Per-block inline dtype detect: for int64 (little-endian) edge indices, all
// odd 32-bit words of the first 256 entries are zero. Returns 1 if int64.
__device__ __forceinline__ int detect_i64(const unsigned int* w, unsigned* s_or) {
    if (threadIdx.x == 0) *s_or = 0u;
    __syncthreads();
    if (threadIdx.x < 128) {
        unsigned v = w[2 * threadIdx.x + 1] | w[2 * threadIdx.x + 257];
        if (v) atomicOr(s_or, 1u);
    }
    __syncthreads();
    return (*s_or == 0u) ? 1 : 0;
}

// ---------------- K0: histogram of in-degrees (inline dtype detect) --------
__global__ void k_count(const void* __restrict__ ei, int E) {
    __shared__ unsigned s_or;
    int is64 = detect_i64((const unsigned int*)ei, &s_or);
    int e = blockIdx.x * blockDim.x + threadIdx.x;
    if (e >= E) return;
    int d;
    if (is64) d = (int)((const long long*)ei)[(size_t)E + e];
    else      d = ((const int*)ei)[E + e];
    atomicAdd(&g_deg[d], 1);
}

// ---------------- K1: merged exclusive scan (redundant global prefix) ------
// Each block sums all degrees before its 1024-chunk (cheap: <=97K ints with
// 1024 threads), then does a local scan and writes g_off/g_cur.
__global__ __launch_bounds__(1024) void k_scan(int n, int E) {
    __shared__ int red[32];
    __shared__ int wpre[32];
    int t = threadIdx.x;
    int lane = t & 31;
    int wid = t >> 5;
    int chunk0 = blockIdx.x << 10;

    // global prefix = sum g_deg[0 .. chunk0)
    int pre = 0;
    for (int i = t; i < chunk0; i += 1024) pre += g_deg[i];
#pragma unroll
    for (int o = 16; o >= 1; o >>= 1) pre += __shfl_xor_sync(0xffffffffu, pre, o);
    if (lane == 0) red[wid] = pre;
    __syncthreads();
    if (t < 32) {
        int v = red[t];
#pragma unroll
        for (int o = 16; o >= 1; o >>= 1) v += __shfl_xor_sync(0xffffffffu, v, o);
        if (t == 0) red[0] = v;
    }
    __syncthreads();
    int prefix = red[0];
    __syncthreads();   // red reused below? no, wpre separate — keep for safety

    // local exclusive scan of this 1024-chunk
    int i = chunk0 + t;
    int d = (i < n) ? g_deg[i] : 0;
    int inc = d;
#pragma unroll
    for (int o = 1; o < 32; o <<= 1) {
        int v = __shfl_up_sync(0xffffffffu, inc, o);
        if (lane >= o) inc += v;
    }
    if (lane == 31) wpre[wid] = inc;
    __syncthreads();
    if (wid == 0) {
        int s = wpre[lane];
        int si = s;
#pragma unroll
        for (int o = 1; o < 32; o <<= 1) {
            int v = __shfl_up_sync(0xffffffffu, si, o);
            if (lane >= o) si += v;
        }
        wpre[lane] = si - s;   // exclusive warp prefix
    }
    __syncthreads();
    if (i < n) {
        int off = prefix + inc - d + wpre[wid];
        g_off[i] = off;
        g_cur[i] = off;
    }
    if (blockIdx.x == gridDim.x - 1 && t == 0) g_off[n] = E;
}

// ---------------- K2: scatter src into CSR buckets + re-zero g_deg ---------
__global__ void k_scatter(const void* __restrict__ ei, int E, int n) {
    __shared__ unsigned s_or;
    int is64 = detect_i64((const unsigned int*)ei, &s_or);
    int e = blockIdx.x * blockDim.x + threadIdx.x;
    if (e < n) g_deg[e] = 0;   // reset for next invocation (unused after scan)
    if (e >= E) return;
    int s, d;
    if (is64) {
        const long long* p = (const long long*)ei;
        s = (int)p[e];
        d = (int)p[(size_t)E + e];
    } else {
        const int* p = (const int*)ei;
        s = p[e];
        d = p[E + e];
    }
    int pos = atomicAdd(&g_cur[d], 1);
    g_csr[pos] = s;
}

// ---------------- K3: warp-specialized gather-max + GEMM + log_softmax -----
// Per block: 64 nodes, 256 threads.
//   Warps 0-3 (G): gather-max neighborhoods (16 nodes/warp) -> As_agg smem.
//   Warps 4-7 (C): concurrently compute the x @ Wr^T half (K=128) with
//                  Xs/Bs chunk staging and private barriers (bar.sync 1,128).
//   Join (bar.sync 0,256), then all stage Wl chunks while C warps accumulate
//   the agg @ Wl^T half; C warps run bias + log_softmax epilogue.
#define SMEM_FLOATS (128 * 65 + 32 * 65 + 32 * 68)
__global__ __launch_bounds__(256) void k_aggemm(const float* __restrict__ x,
                                                const float* __restrict__ Wl,
                                                const float* __restrict__ bl,
                                                const float* __restrict__ Wr,
                                                float* __restrict__ out, int N) {
    extern __shared__ float smem[];
    float (*As_agg)[65] = (float(*)[65])smem;                       // [128][65]
    float (*Xs)[65]     = (float(*)[65])(smem + 128 * 65);          // [32][65]
    float (*Bs)[68]     = (float(*)[68])(smem + 128 * 65 + 32 * 65);// [32][68]

    int t = threadIdx.x;
    int w = t >> 5;
    int lane = t & 31;
    int nb = blockIdx.x * 64;

    // C-thread microtile coords (warps 4-7): 4 nodes x 8 outputs each.
    int ct = t - 128;            // 0..127 for C warps
    int tx = ct & 7;             // output group: cols tx*8 .. tx*8+7
    int ty = ct >> 3;            // node group: nodes ty*4 .. ty*4+3
    float acc[4][8];

    if (w < 4) {
        // ---------------- G warps: gather-max into As_agg ----------------
        const float4* xv = (const float4*)x;
#pragma unroll 1
        for (int r = 0; r < 16; r++) {
            int ln = w * 16 + r;
            int n = nb + ln;
            float4 a = make_float4(0.f, 0.f, 0.f, 0.f);
            if (n < N) {
                int beg = g_off[n];
                int end = g_off[n + 1];
                if (beg < end) {
                    a = make_float4(-CUDART_INF_F, -CUDART_INF_F,
                                    -CUDART_INF_F, -CUDART_INF_F);
                    int e = beg;
                    for (; e + 3 < end; e += 4) {
                        int s0 = g_csr[e];
                        int s1 = g_csr[e + 1];
                        int s2 = g_csr[e + 2];
                        int s3 = g_csr[e + 3];
                        float4 v0 = xv[(size_t)s0 * 32 + lane];
                        float4 v1 = xv[(size_t)s1 * 32 + lane];
                        float4 v2 = xv[(size_t)s2 * 32 + lane];
                        float4 v3 = xv[(size_t)s3 * 32 + lane];
                        a.x = fmaxf(a.x, fmaxf(fmaxf(v0.x, v1.x), fmaxf(v2.x, v3.x)));
                        a.y = fmaxf(a.y, fmaxf(fmaxf(v0.y, v1.y), fmaxf(v2.y, v3.y)));
                        a.z = fmaxf(a.z, fmaxf(fmaxf(v0.z, v1.z), fmaxf(v2.z, v3.z)));
                        a.w = fmaxf(a.w, fmaxf(fmaxf(v0.w, v1.w), fmaxf(v2.w, v3.w)));
                    }
                    for (; e < end; e++) {
                        int s0 = g_csr[e];
                        float4 v0 = xv[(size_t)s0 * 32 + lane];
                        a.x = fmaxf(a.x, v0.x);
                        a.y = fmaxf(a.y, v0.y);
                        a.z = fmaxf(a.z, v0.z);
                        a.w = fmaxf(a.w, v0.w);
                    }
                }
            }
            As_agg[lane * 4 + 0][ln] = a.x;
            As_agg[lane * 4 + 1][ln] = a.y;
            As_agg[lane * 4 + 2][ln] = a.z;
            As_agg[lane * 4 + 3][ln] = a.w;
        }
        asm volatile("bar.sync 0, 256;" ::: "memory");   // join
    } else {
        // ---------------- C warps: x @ Wr^T half (K=128) -----------------
#pragma unroll
        for (int i = 0; i < 4; i++)
#pragma unroll
            for (int j = 0; j < 8; j++) acc[i][j] = 0.f;

        int kq  = (ct & 7) * 4;   // staging k offset (0..28)
        int row = ct >> 3;        // staging row (0..15)

        for (int kb = 0; kb < 128; kb += 32) {
#pragma unroll
            for (int r2 = 0; r2 < 4; r2++) {
                int c = row + r2 * 16;   // 0..63
                // x tile chunk
                int n = nb + c;
                float4 v = (n < N)
                    ? *(const float4*)(x + (size_t)n * D_IN + kb + kq)
                    : make_float4(0.f, 0.f, 0.f, 0.f);
                Xs[kq + 0][c] = v.x;
                Xs[kq + 1][c] = v.y;
                Xs[kq + 2][c] = v.z;
                Xs[kq + 3][c] = v.w;
                // Wr tile chunk
                float4 wv = *(const float4*)(Wr + (size_t)c * D_IN + kb + kq);
                Bs[kq + 0][c] = wv.x;
                Bs[kq + 1][c] = wv.y;
                Bs[kq + 2][c] = wv.z;
                Bs[kq + 3][c] = wv.w;
            }
            asm volatile("bar.sync 1, 128;" ::: "memory");
#pragma unroll
            for (int kk = 0; kk < 32; kk++) {
                float a0 = Xs[kk][ty * 4 + 0];
                float a1 = Xs[kk][ty * 4 + 1];
                float a2 = Xs[kk][ty * 4 + 2];
                float a3 = Xs[kk][ty * 4 + 3];
                float4 blo = *(const float4*)&Bs[kk][tx * 8];
                float4 bhi = *(const float4*)&Bs[kk][tx * 8 + 4];
                float b[8] = {blo.x, blo.y, blo.z, blo.w,
                              bhi.x, bhi.y, bhi.z, bhi.w};
#pragma unroll
                for (int j = 0; j < 8; j++) {
                    acc[0][j] += a0 * b[j];
                    acc[1][j] += a1 * b[j];
                    acc[2][j] += a2 * b[j];
                    acc[3][j] += a3 * b[j];
                }
            }
            asm volatile("bar.sync 1, 128;" ::: "memory");
        }
        asm volatile("bar.sync 0, 256;" ::: "memory");   // join
    }

    // ---------------- all warps: agg @ Wl^T half (K=128) -----------------
    {
        int kq  = (t & 7) * 4;   // staging k offset (0..28)
        int row = t >> 3;        // staging row (0..31)
        for (int kb = 0; kb < 128; kb += 32) {
#pragma unroll
            for (int r2 = 0; r2 < 2; r2++) {
                int c = row + r2 * 32;   // 0..63
                float4 wv = *(const float4*)(Wl + (size_t)c * D_IN + kb + kq);
                Bs[kq + 0][c] = wv.x;
                Bs[kq + 1][c] = wv.y;
                Bs[kq + 2][c] = wv.z;
                Bs[kq + 3][c] = wv.w;
            }
            __syncthreads();
            if (w >= 4) {
                const float (*Arows)[65] = As_agg + kb;
#pragma unroll
                for (int kk = 0; kk < 32; kk++) {
                    float a0 = Arows[kk][ty * 4 + 0];
                    float a1 = Arows[kk][ty * 4 + 1];
                    float a2 = Arows[kk][ty * 4 + 2];
                    float a3 = Arows[kk][ty * 4 + 3];
                    float4 blo = *(const float4*)&Bs[kk][tx * 8];
                    float4 bhi = *(const float4*)&Bs[kk][tx * 8 + 4];
                    float b[8] = {blo.x, blo.y, blo.z, blo.w,
                                  bhi.x, bhi.y, bhi.z, bhi.w};
#pragma unroll
                    for (int j = 0; j < 8; j++) {
                        acc[0][j] += a0 * b[j];
                        acc[1][j] += a1 * b[j];
                        acc[2][j] += a2 * b[j];
                        acc[3][j] += a3 * b[j];
                    }
                }
            }
            __syncthreads();
        }
    }

    // ---------------- C warps: bias + log_softmax + store ----------------
    if (w >= 4) {
        float bv[8];
#pragma unroll
        for (int j = 0; j < 8; j++) bv[j] = bl[tx * 8 + j];
#pragma unroll
        for (int i = 0; i < 4; i++)
#pragma unroll
            for (int j = 0; j < 8; j++) acc[i][j] += bv[j];

        // node (nb + ty*4 + i)'s 64 outputs live in the 8 lanes sharing ty.
#pragma unroll
        for (int i = 0; i < 4; i++) {
            float m = acc[i][0];
#pragma unroll
            for (int j = 1; j < 8; j++) m = fmaxf(m, acc[i][j]);
#pragma unroll
            for (int o = 4; o >= 1; o >>= 1)
                m = fmaxf(m, __shfl_xor_sync(0xffffffffu, m, o));
            float s = 0.f;
#pragma unroll
            for (int j = 0; j < 8; j++) s += expf(acc[i][j] - m);
#pragma unroll
            for (int o = 4; o >= 1; o >>= 1)
                s += __shfl_xor_sync(0xffffffffu, s, o);
            float lse = m + logf(s);

            int n = nb + ty * 4 + i;
            if (n < N) {
                float4 o0 = make_float4(acc[i][0] - lse, acc[i][1] - lse,
                                        acc[i][2] - lse, acc[i][3] - lse);
                float4 o1 = make_float4(acc[i][4] - lse, acc[i][5] - lse,
                                        acc[i][6] - lse, acc[i][7] - lse);
                *(float4*)(out + (size_t)n * D_OUT + tx * 8) = o0;
                *(float4*)(out + (size_t)n * D_OUT + tx * 8 + 4) = o1;
            }
        }
    }
}

// ---------------- launcher -------------------------------------------------
extern "C" void kernel_launch(void* const* d_in, const int* in_sizes, int n_in,
                              void* d_out, int out_size) {
    const float* x  = (const float*)d_in[0];
    const void*  ei = d_in[1];
    const float* Wl = (const float*)d_in[2];
    const float* bl = (const float*)d_in[3];
    const float* Wr = (const float*)d_in[4];
    float* out = (float*)d_out;

    int N = in_sizes[0] / D_IN;
    int E = in_sizes[1] / 2;

    const int smem_bytes = SMEM_FLOATS * (int)sizeof(float);   // 50304
    cudaFuncSetAttribute(k_aggemm, cudaFuncAttributeMaxDynamicSharedMemorySize,
                         smem_bytes);

    // Launch order: ncu's -s 5 -c 1 profiles OUR index 3 => k_aggemm.
    k_count<<<(E + 255) / 256, 256>>>(ei, E);                              // 0
    k_scan<<<(N + 1023) / 1024, 1024>>>(N, E);                             // 1
    k_scatter<<<(E + 255) / 256, 256>>>(ei, E, N);                         // 2
    k_aggemm<<<(N + 63) / 64, 256, smem_bytes>>>(x, Wl, bl, Wr, out, N);   // 3
}

// round 8
// speedup vs baseline: 1.3022x; 1.2637x over previous
#include <cuda_runtime.h>
#include <math_constants.h>
#include <stdint.h>

// Problem constants (shapes fixed by the reference).
#define MAX_N 100032
#define MAX_E 1600000
#define D_IN  128
#define D_OUT 64

// ---------------- Scratch (static __device__ globals; no runtime allocs) ---
// g_deg is zero at module load; k_scatter re-zeroes it for the NEXT invocation
// (graph replays run the identical sequence, so the invariant holds).
__device__ int g_deg[MAX_N];
__device__ int g_off[MAX_N + 1];
__device__ int g_cur[MAX_N];
__device__ int g_csr[MAX_E];              // src indices grouped by dst

// Per-block inline dtype detect: for int64 (little-endian) edge indices, all
// odd 32-bit words of the first 256 entries are zero. Returns 1 if int64.
__device__ __forceinline__ int detect_i64(const unsigned int* w, unsigned* s_or) {
    if (threadIdx.x == 0) *s_or = 0u;
    __syncthreads();
    if (threadIdx.x < 128) {
        unsigned v = w[2 * threadIdx.x + 1] | w[2 * threadIdx.x + 257];
        if (v) atomicOr(s_or, 1u);
    }
    __syncthreads();
    return (*s_or == 0u) ? 1 : 0;
}

// ---------------- K0: histogram of in-degrees (inline dtype detect) --------
__global__ void k_count(const void* __restrict__ ei, int E) {
    __shared__ unsigned s_or;
    int is64 = detect_i64((const unsigned int*)ei, &s_or);
    int e = blockIdx.x * blockDim.x + threadIdx.x;
    if (e >= E) return;
    int d;
    if (is64) d = (int)((const long long*)ei)[(size_t)E + e];
    else      d = ((const int*)ei)[E + e];
    atomicAdd(&g_deg[d], 1);
}

// ---------------- K1: merged exclusive scan (redundant global prefix) ------
__global__ __launch_bounds__(1024) void k_scan(int n, int E) {
    __shared__ int red[32];
    __shared__ int wpre[32];
    int t = threadIdx.x;
    int lane = t & 31;
    int wid = t >> 5;
    int chunk0 = blockIdx.x << 10;

    int pre = 0;
    for (int i = t; i < chunk0; i += 1024) pre += g_deg[i];
#pragma unroll
    for (int o = 16; o >= 1; o >>= 1) pre += __shfl_xor_sync(0xffffffffu, pre, o);
    if (lane == 0) red[wid] = pre;
    __syncthreads();
    if (t < 32) {
        int v = red[t];
#pragma unroll
        for (int o = 16; o >= 1; o >>= 1) v += __shfl_xor_sync(0xffffffffu, v, o);
        if (t == 0) red[0] = v;
    }
    __syncthreads();
    int prefix = red[0];

    int i = chunk0 + t;
    int d = (i < n) ? g_deg[i] : 0;
    int inc = d;
#pragma unroll
    for (int o = 1; o < 32; o <<= 1) {
        int v = __shfl_up_sync(0xffffffffu, inc, o);
        if (lane >= o) inc += v;
    }
    if (lane == 31) wpre[wid] = inc;
    __syncthreads();
    if (wid == 0) {
        int s = wpre[lane];
        int si = s;
#pragma unroll
        for (int o = 1; o < 32; o <<= 1) {
            int v = __shfl_up_sync(0xffffffffu, si, o);
            if (lane >= o) si += v;
        }
        wpre[lane] = si - s;
    }
    __syncthreads();
    if (i < n) {
        int off = prefix + inc - d + wpre[wid];
        g_off[i] = off;
        g_cur[i] = off;
    }
    if (blockIdx.x == gridDim.x - 1 && t == 0) g_off[n] = E;
}

// ---------------- K2: scatter src into CSR buckets + re-zero g_deg ---------
__global__ void k_scatter(const void* __restrict__ ei, int E, int n) {
    __shared__ unsigned s_or;
    int is64 = detect_i64((const unsigned int*)ei, &s_or);
    int e = blockIdx.x * blockDim.x + threadIdx.x;
    if (e < n) g_deg[e] = 0;
    if (e >= E) return;
    int s, d;
    if (is64) {
        const long long* p = (const long long*)ei;
        s = (int)p[e];
        d = (int)p[(size_t)E + e];
    } else {
        const int* p = (const int*)ei;
        s = p[e];
        d = p[E + e];
    }
    int pos = atomicAdd(&g_cur[d], 1);
    g_csr[pos] = s;
}

// ---------------- K3: fused gather-max + GEMM + bias + log_softmax ---------
// Per block: 64 nodes, 256 threads, uniform warps. Three phases:
//   G: gather-max neighborhoods -> As[node][k] (coalesced STS.128)
//   L: acc += agg @ Wl^T (reads As, K=128, Bs chunked)
//   X: stage x -> As, acc += x @ Wr^T
// Even blocks run G,L,X; odd blocks run X,G,L -> at any instant about half
// the resident warps are in the LTS-bound gather and half in FFMA phases,
// overlapping the two chip-level floors.
__global__ __launch_bounds__(256) void k_aggemm(const float* __restrict__ x,
                                                const float* __restrict__ Wl,
                                                const float* __restrict__ bl,
                                                const float* __restrict__ Wr,
                                                float* __restrict__ out, int N) {
    __shared__ float As[64][132];   // node-major; 132%4==0 keeps float4 aligned
    __shared__ float Bs[32][68];    // k-major weight chunk

    int t = threadIdx.x;
    int w = t >> 5;
    int lane = t & 31;
    int nb = blockIdx.x * 64;
    int tx = t & 15;      // output group: cols tx*4..tx*4+3
    int ty = t >> 4;      // node group: nodes ty*4..ty*4+3

    float acc[4][4];
#pragma unroll
    for (int i = 0; i < 4; i++)
#pragma unroll
        for (int j = 0; j < 4; j++) acc[i][j] = 0.f;

    // ---- phase G: gather-max into As (node-major) ----
    auto phaseG = [&]() {
        const float4* xv = (const float4*)x;
#pragma unroll 1
        for (int r = 0; r < 8; r++) {
            int ln = w * 8 + r;
            int n = nb + ln;
            float4 a = make_float4(0.f, 0.f, 0.f, 0.f);
            if (n < N) {
                int beg = g_off[n];
                int end = g_off[n + 1];
                if (beg < end) {
                    a = make_float4(-CUDART_INF_F, -CUDART_INF_F,
                                    -CUDART_INF_F, -CUDART_INF_F);
                    int e = beg;
                    for (; e + 3 < end; e += 4) {
                        int s0 = g_csr[e];
                        int s1 = g_csr[e + 1];
                        int s2 = g_csr[e + 2];
                        int s3 = g_csr[e + 3];
                        float4 v0 = xv[(size_t)s0 * 32 + lane];
                        float4 v1 = xv[(size_t)s1 * 32 + lane];
                        float4 v2 = xv[(size_t)s2 * 32 + lane];
                        float4 v3 = xv[(size_t)s3 * 32 + lane];
                        a.x = fmaxf(a.x, fmaxf(fmaxf(v0.x, v1.x), fmaxf(v2.x, v3.x)));
                        a.y = fmaxf(a.y, fmaxf(fmaxf(v0.y, v1.y), fmaxf(v2.y, v3.y)));
                        a.z = fmaxf(a.z, fmaxf(fmaxf(v0.z, v1.z), fmaxf(v2.z, v3.z)));
                        a.w = fmaxf(a.w, fmaxf(fmaxf(v0.w, v1.w), fmaxf(v2.w, v3.w)));
                    }
                    for (; e < end; e++) {
                        int s0 = g_csr[e];
                        float4 v0 = xv[(size_t)s0 * 32 + lane];
                        a.x = fmaxf(a.x, v0.x);
                        a.y = fmaxf(a.y, v0.y);
                        a.z = fmaxf(a.z, v0.z);
                        a.w = fmaxf(a.w, v0.w);
                    }
                }
            }
            *(float4*)&As[ln][lane * 4] = a;   // coalesced STS.128
        }
        __syncthreads();
    };

    // ---- GEMM half over K=128 reading As, weights W chunked via Bs ----
    auto gemmHalf = [&](const float* __restrict__ W) {
        int kq = (t & 7) * 4;   // staging k offset (0..28)
        int c0 = t >> 3;        // staging col (0..31)
        for (int kb = 0; kb < 128; kb += 32) {
#pragma unroll
            for (int r2 = 0; r2 < 2; r2++) {
                int c = c0 + r2 * 32;
                float4 wv = *(const float4*)(W + (size_t)c * D_IN + kb + kq);
                Bs[kq + 0][c] = wv.x;
                Bs[kq + 1][c] = wv.y;
                Bs[kq + 2][c] = wv.z;
                Bs[kq + 3][c] = wv.w;
            }
            __syncthreads();
#pragma unroll
            for (int kk4 = 0; kk4 < 32; kk4 += 4) {
                float4 a0 = *(const float4*)&As[ty * 4 + 0][kb + kk4];
                float4 a1 = *(const float4*)&As[ty * 4 + 1][kb + kk4];
                float4 a2 = *(const float4*)&As[ty * 4 + 2][kb + kk4];
                float4 a3 = *(const float4*)&As[ty * 4 + 3][kb + kk4];
#pragma unroll
                for (int u = 0; u < 4; u++) {
                    float4 b = *(const float4*)&Bs[kk4 + u][tx * 4];
                    float e0 = (u == 0) ? a0.x : (u == 1) ? a0.y : (u == 2) ? a0.z : a0.w;
                    float e1 = (u == 0) ? a1.x : (u == 1) ? a1.y : (u == 2) ? a1.z : a1.w;
                    float e2 = (u == 0) ? a2.x : (u == 1) ? a2.y : (u == 2) ? a2.z : a2.w;
                    float e3 = (u == 0) ? a3.x : (u == 1) ? a3.y : (u == 2) ? a3.z : a3.w;
                    acc[0][0] += e0 * b.x; acc[0][1] += e0 * b.y; acc[0][2] += e0 * b.z; acc[0][3] += e0 * b.w;
                    acc[1][0] += e1 * b.x; acc[1][1] += e1 * b.y; acc[1][2] += e1 * b.z; acc[1][3] += e1 * b.w;
                    acc[2][0] += e2 * b.x; acc[2][1] += e2 * b.y; acc[2][2] += e2 * b.z; acc[2][3] += e2 * b.w;
                    acc[3][0] += e3 * b.x; acc[3][1] += e3 * b.y; acc[3][2] += e3 * b.z; acc[3][3] += e3 * b.w;
                }
            }
            __syncthreads();
        }
    };

    // ---- phase X: stage x into As, then x @ Wr^T ----
    auto phaseX = [&]() {
        int node = t >> 2;           // 0..63
        int kbase = (t & 3) * 32;    // 0,32,64,96
#pragma unroll
        for (int j = 0; j < 8; j++) {
            int k4 = kbase + j * 4;
            int n = nb + node;
            float4 v = (n < N) ? *(const float4*)(x + (size_t)n * D_IN + k4)
                               : make_float4(0.f, 0.f, 0.f, 0.f);
            *(float4*)&As[node][k4] = v;
        }
        __syncthreads();
        gemmHalf(Wr);
    };

    if (blockIdx.x & 1) {
        phaseX();          // FFMA first ...
        phaseG();          // ... while even blocks gather
        gemmHalf(Wl);
    } else {
        phaseG();
        gemmHalf(Wl);
        phaseX();
    }

    // ---- epilogue: bias + log_softmax + store ----
    float bv[4];
#pragma unroll
    for (int j = 0; j < 4; j++) bv[j] = bl[tx * 4 + j];
#pragma unroll
    for (int i = 0; i < 4; i++)
#pragma unroll
        for (int j = 0; j < 4; j++) acc[i][j] += bv[j];

    // node (nb + ty*4 + i)'s 64 outputs live in the 16 lanes sharing ty.
#pragma unroll
    for (int i = 0; i < 4; i++) {
        float m = acc[i][0];
        m = fmaxf(m, acc[i][1]);
        m = fmaxf(m, acc[i][2]);
        m = fmaxf(m, acc[i][3]);
#pragma unroll
        for (int o = 8; o >= 1; o >>= 1)
            m = fmaxf(m, __shfl_xor_sync(0xffffffffu, m, o));
        float s = expf(acc[i][0] - m) + expf(acc[i][1] - m) +
                  expf(acc[i][2] - m) + expf(acc[i][3] - m);
#pragma unroll
        for (int o = 8; o >= 1; o >>= 1)
            s += __shfl_xor_sync(0xffffffffu, s, o);
        float lse = m + logf(s);

        int n = nb + ty * 4 + i;
        if (n < N) {
            float4 o4 = make_float4(acc[i][0] - lse, acc[i][1] - lse,
                                    acc[i][2] - lse, acc[i][3] - lse);
            *(float4*)(out + (size_t)n * D_OUT + tx * 4) = o4;
        }
    }
}

// ---------------- launcher -------------------------------------------------
extern "C" void kernel_launch(void* const* d_in, const int* in_sizes, int n_in,
                              void* d_out, int out_size) {
    const float* x  = (const float*)d_in[0];
    const void*  ei = d_in[1];
    const float* Wl = (const float*)d_in[2];
    const float* bl = (const float*)d_in[3];
    const float* Wr = (const float*)d_in[4];
    float* out = (float*)d_out;

    int N = in_sizes[0] / D_IN;
    int E = in_sizes[1] / 2;

    // Launch order: ncu profiles OUR index 3 => k_aggemm.
    k_count<<<(E + 255) / 256, 256>>>(ei, E);                       // 0
    k_scan<<<(N + 1023) / 1024, 1024>>>(N, E);                      // 1
    k_scatter<<<(E + 255) / 256, 256>>>(ei, E, N);                  // 2
    k_aggemm<<<(N + 63) / 64, 256>>>(x, Wl, bl, Wr, out, N);        // 3
}

// round 9
// speedup vs baseline: 1.3688x; 1.0511x over previous
#include <cuda_runtime.h>
#include <math_constants.h>
#include <stdint.h>

// Problem constants (shapes fixed by the reference).
#define MAX_N 100032
#define MAX_E 1600000
#define D_IN  128
#define D_OUT 64

#define AS_PAD 132   // As row pitch: banks (4*qid + tig) all-distinct for A frags
#define BS_PAD 72    // Bs row pitch: banks (8*tig + qid) all-distinct for B frags
#define OS_PAD 68    // epilogue pitch

// ---------------- Scratch (static __device__ globals; no runtime allocs) ---
// g_deg is zero at module load; k_scatter re-zeroes it for the NEXT invocation
// (graph replays run the identical sequence, so the invariant holds).
__device__ int g_deg[MAX_N];
__device__ int g_off[MAX_N + 1];
__device__ int g_cur[MAX_N];
__device__ int g_csr[MAX_E];              // src indices grouped by dst

// Per-block inline dtype detect: for int64 (little-endian) edge indices, all
// odd 32-bit words of the first 256 entries are zero. Returns 1 if int64.
__device__ __forceinline__ int detect_i64(const unsigned int* w, unsigned* s_or) {
    if (threadIdx.x == 0) *s_or = 0u;
    __syncthreads();
    if (threadIdx.x < 128) {
        unsigned v = w[2 * threadIdx.x + 1] | w[2 * threadIdx.x + 257];
        if (v) atomicOr(s_or, 1u);
    }
    __syncthreads();
    return (*s_or == 0u) ? 1 : 0;
}

// ---------------- K0: histogram of in-degrees (inline dtype detect) --------
__global__ void k_count(const void* __restrict__ ei, int E) {
    __shared__ unsigned s_or;
    int is64 = detect_i64((const unsigned int*)ei, &s_or);
    int e = blockIdx.x * blockDim.x + threadIdx.x;
    if (e >= E) return;
    int d;
    if (is64) d = (int)((const long long*)ei)[(size_t)E + e];
    else      d = ((const int*)ei)[E + e];
    atomicAdd(&g_deg[d], 1);
}

// ---------------- K1: merged exclusive scan (redundant global prefix) ------
__global__ __launch_bounds__(1024) void k_scan(int n, int E) {
    __shared__ int red[32];
    __shared__ int wpre[32];
    int t = threadIdx.x;
    int lane = t & 31;
    int wid = t >> 5;
    int chunk0 = blockIdx.x << 10;

    int pre = 0;
    for (int i = t; i < chunk0; i += 1024) pre += g_deg[i];
#pragma unroll
    for (int o = 16; o >= 1; o >>= 1) pre += __shfl_xor_sync(0xffffffffu, pre, o);
    if (lane == 0) red[wid] = pre;
    __syncthreads();
    if (t < 32) {
        int v = red[t];
#pragma unroll
        for (int o = 16; o >= 1; o >>= 1) v += __shfl_xor_sync(0xffffffffu, v, o);
        if (t == 0) red[0] = v;
    }
    __syncthreads();
    int prefix = red[0];

    int i = chunk0 + t;
    int d = (i < n) ? g_deg[i] : 0;
    int inc = d;
#pragma unroll
    for (int o = 1; o < 32; o <<= 1) {
        int v = __shfl_up_sync(0xffffffffu, inc, o);
        if (lane >= o) inc += v;
    }
    if (lane == 31) wpre[wid] = inc;
    __syncthreads();
    if (wid == 0) {
        int s = wpre[lane];
        int si = s;
#pragma unroll
        for (int o = 1; o < 32; o <<= 1) {
            int v = __shfl_up_sync(0xffffffffu, si, o);
            if (lane >= o) si += v;
        }
        wpre[lane] = si - s;
    }
    __syncthreads();
    if (i < n) {
        int off = prefix + inc - d + wpre[wid];
        g_off[i] = off;
        g_cur[i] = off;
    }
    if (blockIdx.x == gridDim.x - 1 && t == 0) g_off[n] = E;
}

// ---------------- K2: scatter src into CSR buckets + re-zero g_deg ---------
__global__ void k_scatter(const void* __restrict__ ei, int E, int n) {
    __shared__ unsigned s_or;
    int is64 = detect_i64((const unsigned int*)ei, &s_or);
    int e = blockIdx.x * blockDim.x + threadIdx.x;
    if (e < n) g_deg[e] = 0;
    if (e >= E) return;
    int s, d;
    if (is64) {
        const long long* p = (const long long*)ei;
        s = (int)p[e];
        d = (int)p[(size_t)E + e];
    } else {
        const int* p = (const int*)ei;
        s = p[e];
        d = p[E + e];
    }
    int pos = atomicAdd(&g_cur[d], 1);
    g_csr[pos] = s;
}

// ---------------- tf32 helpers ---------------------------------------------
__device__ __forceinline__ uint32_t f2tf32(float a) {
    uint32_t r;
    asm("cvt.rna.tf32.f32 %0, %1;" : "=r"(r) : "f"(a));
    return r;
}

__device__ __forceinline__ void mma_tf32(float* d,
                                         uint32_t a0, uint32_t a1,
                                         uint32_t a2, uint32_t a3,
                                         uint32_t b0, uint32_t b1) {
    asm volatile(
        "mma.sync.aligned.m16n8k8.row.col.f32.tf32.tf32.f32 "
        "{%0,%1,%2,%3}, {%4,%5,%6,%7}, {%8,%9}, {%0,%1,%2,%3};"
        : "+f"(d[0]), "+f"(d[1]), "+f"(d[2]), "+f"(d[3])
        : "r"(a0), "r"(a1), "r"(a2), "r"(a3), "r"(b0), "r"(b1));
}

// ---------------- K3: fused gather-max + 3xTF32 MMA + log_softmax ----------
// Per block: 64 nodes, 256 threads (8 warps).
//   G: gather-max neighborhoods -> As[node][k] (coalesced STS.128)
//   L: acc += agg @ Wl^T via mma.sync (reads As, Bs chunked)
//   X: stage x -> As, acc += x @ Wr^T via mma.sync
// Even blocks run G,L,X; odd blocks X,G,L -> chip-level overlap of the
// LTS-bound gather with the tensor/LDS-bound GEMM phases.
// Warp tiling: warp_m = w>>1 (16 nodes), warp_n = w&1 (32 outs, 4 n-tiles).
__global__ __launch_bounds__(256) void k_aggemm(const float* __restrict__ x,
                                                const float* __restrict__ Wl,
                                                const float* __restrict__ bl,
                                                const float* __restrict__ Wr,
                                                float* __restrict__ out, int N) {
    __shared__ float As[64][AS_PAD];
    __shared__ float Bs[32][BS_PAD];

    int t = threadIdx.x;
    int w = t >> 5;
    int lane = t & 31;
    int nb = blockIdx.x * 64;

    int qid = lane >> 2;     // 0..7
    int tig = lane & 3;      // 0..3
    int wr = (w >> 1) * 16;  // warp node base
    int wn = (w & 1) * 32;   // warp output base

    float acc[4][4];
#pragma unroll
    for (int i = 0; i < 4; i++)
#pragma unroll
        for (int j = 0; j < 4; j++) acc[i][j] = 0.f;

    // ---- phase G: gather-max into As (node-major) ----
    auto phaseG = [&]() {
        const float4* xv = (const float4*)x;
#pragma unroll 1
        for (int r = 0; r < 8; r++) {
            int ln = w * 8 + r;
            int n = nb + ln;
            float4 a = make_float4(0.f, 0.f, 0.f, 0.f);
            if (n < N) {
                int beg = g_off[n];
                int end = g_off[n + 1];
                if (beg < end) {
                    a = make_float4(-CUDART_INF_F, -CUDART_INF_F,
                                    -CUDART_INF_F, -CUDART_INF_F);
                    int e = beg;
                    for (; e + 3 < end; e += 4) {
                        int s0 = g_csr[e];
                        int s1 = g_csr[e + 1];
                        int s2 = g_csr[e + 2];
                        int s3 = g_csr[e + 3];
                        float4 v0 = xv[(size_t)s0 * 32 + lane];
                        float4 v1 = xv[(size_t)s1 * 32 + lane];
                        float4 v2 = xv[(size_t)s2 * 32 + lane];
                        float4 v3 = xv[(size_t)s3 * 32 + lane];
                        a.x = fmaxf(a.x, fmaxf(fmaxf(v0.x, v1.x), fmaxf(v2.x, v3.x)));
                        a.y = fmaxf(a.y, fmaxf(fmaxf(v0.y, v1.y), fmaxf(v2.y, v3.y)));
                        a.z = fmaxf(a.z, fmaxf(fmaxf(v0.z, v1.z), fmaxf(v2.z, v3.z)));
                        a.w = fmaxf(a.w, fmaxf(fmaxf(v0.w, v1.w), fmaxf(v2.w, v3.w)));
                    }
                    for (; e < end; e++) {
                        int s0 = g_csr[e];
                        float4 v0 = xv[(size_t)s0 * 32 + lane];
                        a.x = fmaxf(a.x, v0.x);
                        a.y = fmaxf(a.y, v0.y);
                        a.z = fmaxf(a.z, v0.z);
                        a.w = fmaxf(a.w, v0.w);
                    }
                }
            }
            *(float4*)&As[ln][lane * 4] = a;   // coalesced STS.128
        }
        __syncthreads();
    };

    // ---- MMA half over K=128 reading As, W chunked through Bs -------------
    auto mmaHalf = [&](const float* __restrict__ W) {
        int kq = (t & 7) * 4;   // staging k offset (0..28)
        int c0 = t >> 3;        // staging col (0..31)
        for (int kb = 0; kb < 128; kb += 32) {
#pragma unroll
            for (int r2 = 0; r2 < 2; r2++) {
                int c = c0 + r2 * 32;
                float4 wv = *(const float4*)(W + (size_t)c * D_IN + kb + kq);
                Bs[kq + 0][c] = wv.x;
                Bs[kq + 1][c] = wv.y;
                Bs[kq + 2][c] = wv.z;
                Bs[kq + 3][c] = wv.w;
            }
            __syncthreads();
#pragma unroll
            for (int ks = 0; ks < 4; ks++) {
                int k0 = kb + ks * 8;
                // A fragment (m16k8 tf32): conflict-free (banks 4*qid+tig)
                float a0f = As[wr + qid][k0 + tig];
                float a1f = As[wr + qid + 8][k0 + tig];
                float a2f = As[wr + qid][k0 + tig + 4];
                float a3f = As[wr + qid + 8][k0 + tig + 4];
                uint32_t a0h = f2tf32(a0f), a1h = f2tf32(a1f);
                uint32_t a2h = f2tf32(a2f), a3h = f2tf32(a3f);
                uint32_t a0l = __float_as_uint(a0f - __uint_as_float(a0h));
                uint32_t a1l = __float_as_uint(a1f - __uint_as_float(a1h));
                uint32_t a2l = __float_as_uint(a2f - __uint_as_float(a2h));
                uint32_t a3l = __float_as_uint(a3f - __uint_as_float(a3h));
#pragma unroll
                for (int tile = 0; tile < 4; tile++) {
                    int col = wn + tile * 8 + qid;
                    // B fragment (k8n8 tf32): conflict-free (banks 8*tig+qid)
                    float b0f = Bs[ks * 8 + tig][col];
                    float b1f = Bs[ks * 8 + tig + 4][col];
                    uint32_t b0h = f2tf32(b0f), b1h = f2tf32(b1f);
                    uint32_t b0l = __float_as_uint(b0f - __uint_as_float(b0h));
                    uint32_t b1l = __float_as_uint(b1f - __uint_as_float(b1h));
                    mma_tf32(acc[tile], a0h, a1h, a2h, a3h, b0h, b1h);
                    mma_tf32(acc[tile], a0l, a1l, a2l, a3l, b0h, b1h);
                    mma_tf32(acc[tile], a0h, a1h, a2h, a3h, b0l, b1l);
                }
            }
            __syncthreads();
        }
    };

    // ---- phase X: stage x into As, then x @ Wr^T ----
    auto phaseX = [&]() {
        int node = t >> 2;           // 0..63
        int kbase = (t & 3) * 32;    // 0,32,64,96
        int n = nb + node;
#pragma unroll
        for (int j = 0; j < 8; j++) {
            int k4 = kbase + j * 4;
            float4 v = (n < N) ? *(const float4*)(x + (size_t)n * D_IN + k4)
                               : make_float4(0.f, 0.f, 0.f, 0.f);
            *(float4*)&As[node][k4] = v;
        }
        __syncthreads();
        mmaHalf(Wr);
    };

    if (blockIdx.x & 1) {
        phaseX();          // tensor/LDS first ...
        phaseG();          // ... while even blocks gather
        mmaHalf(Wl);
    } else {
        phaseG();
        mmaHalf(Wl);
        phaseX();
    }

    // ---- epilogue: acc fragments -> smem (+bias), then log_softmax --------
    float (*Os)[OS_PAD] = (float(*)[OS_PAD])As;   // overlay (all reads done)
    __syncthreads();
#pragma unroll
    for (int tile = 0; tile < 4; tile++) {
        int c = wn + tile * 8 + 2 * tig;
        int r0 = wr + qid;
        float b0 = bl[c], b1 = bl[c + 1];
        Os[r0][c]         = acc[tile][0] + b0;
        Os[r0][c + 1]     = acc[tile][1] + b1;
        Os[r0 + 8][c]     = acc[tile][2] + b0;
        Os[r0 + 8][c + 1] = acc[tile][3] + b1;
    }
    __syncthreads();

    // softmax: 4 threads per node row, 16 cols each
    {
        int row = t >> 2;
        int l4 = t & 3;
        float4 v[4];
#pragma unroll
        for (int j = 0; j < 4; j++)
            v[j] = *(const float4*)&Os[row][l4 * 16 + j * 4];

        float m = -CUDART_INF_F;
#pragma unroll
        for (int j = 0; j < 4; j++) {
            m = fmaxf(m, fmaxf(fmaxf(v[j].x, v[j].y), fmaxf(v[j].z, v[j].w)));
        }
        m = fmaxf(m, __shfl_xor_sync(0xffffffffu, m, 1));
        m = fmaxf(m, __shfl_xor_sync(0xffffffffu, m, 2));

        float s = 0.f;
#pragma unroll
        for (int j = 0; j < 4; j++) {
            s += expf(v[j].x - m) + expf(v[j].y - m) +
                 expf(v[j].z - m) + expf(v[j].w - m);
        }
        s += __shfl_xor_sync(0xffffffffu, s, 1);
        s += __shfl_xor_sync(0xffffffffu, s, 2);
        float lse = m + logf(s);

        int n = nb + row;
        if (n < N) {
#pragma unroll
            for (int j = 0; j < 4; j++) {
                float4 o4 = make_float4(v[j].x - lse, v[j].y - lse,
                                        v[j].z - lse, v[j].w - lse);
                *(float4*)(out + (size_t)n * D_OUT + l4 * 16 + j * 4) = o4;
            }
        }
    }
}

// ---------------- launcher -------------------------------------------------
extern "C" void kernel_launch(void* const* d_in, const int* in_sizes, int n_in,
                              void* d_out, int out_size) {
    const float* x  = (const float*)d_in[0];
    const void*  ei = d_in[1];
    const float* Wl = (const float*)d_in[2];
    const float* bl = (const float*)d_in[3];
    const float* Wr = (const float*)d_in[4];
    float* out = (float*)d_out;

    int N = in_sizes[0] / D_IN;
    int E = in_sizes[1] / 2;

    // Launch order: ncu profiles OUR index 3 => k_aggemm.
    k_count<<<(E + 255) / 256, 256>>>(ei, E);                       // 0
    k_scan<<<(N + 1023) / 1024, 1024>>>(N, E);                      // 1
    k_scatter<<<(E + 255) / 256, 256>>>(ei, E, N);                  // 2
    k_aggemm<<<(N + 63) / 64, 256>>>(x, Wl, bl, Wr, out, N);        // 3
}

// round 11
// speedup vs baseline: 1.8401x; 1.3443x over previous
#include <cuda_runtime.h>
#include <cuda_fp16.h>
#include <math_constants.h>
#include <stdint.h>

// Problem constants (shapes fixed by the reference).
#define MAX_N 100032
#define MAX_E 1600000
#define D_IN  128
#define D_OUT 64

#define ROW_W 68     // half2-words per smem row (64 data + 4 pad); 272 B, 16B-aligned
#define OS_PAD 68    // epilogue float pitch (overlays Ash exactly)

// ---------------- Scratch (static __device__ globals; no runtime allocs) ---
// g_deg is zero at module load; k_scatter re-zeroes it for the NEXT invocation
// (graph replays run the identical sequence, so the invariant holds).
__device__ int    g_deg[MAX_N];
__device__ int    g_off[MAX_N + 1];
__device__ int    g_cur[MAX_N];
__device__ int    g_csr[MAX_E];                 // src indices grouped by dst
__device__ __half g_xh[(size_t)MAX_N * D_IN];   // fp16 copy of x (25.6 MB)

// Per-block inline dtype detect: for int64 (little-endian) edge indices, all
// odd 32-bit words of the first 256 entries are zero. Returns 1 if int64.
__device__ __forceinline__ int detect_i64(const unsigned int* w, unsigned* s_or) {
    if (threadIdx.x == 0) *s_or = 0u;
    __syncthreads();
    if (threadIdx.x < 128) {
        unsigned v = w[2 * threadIdx.x + 1] | w[2 * threadIdx.x + 257];
        if (v) atomicOr(s_or, 1u);
    }
    __syncthreads();
    return (*s_or == 0u) ? 1 : 0;
}

// ---------------- K0: degree histogram + x -> fp16 conversion --------------
__global__ void k_count(const float* __restrict__ x, const void* __restrict__ ei,
                        int E, int n8) {
    __shared__ unsigned s_or;
    int is64 = detect_i64((const unsigned int*)ei, &s_or);
    int e = blockIdx.x * blockDim.x + threadIdx.x;

    if (e < n8) {   // convert 8 floats -> 8 halves (16 B out)
        const float4* xv4 = (const float4*)x;
        float4 a = xv4[(size_t)e * 2];
        float4 b = xv4[(size_t)e * 2 + 1];
        __half2 h0 = __float22half2_rn(make_float2(a.x, a.y));
        __half2 h1 = __float22half2_rn(make_float2(a.z, a.w));
        __half2 h2 = __float22half2_rn(make_float2(b.x, b.y));
        __half2 h3 = __float22half2_rn(make_float2(b.z, b.w));
        uint4 o;
        o.x = reinterpret_cast<uint32_t&>(h0);
        o.y = reinterpret_cast<uint32_t&>(h1);
        o.z = reinterpret_cast<uint32_t&>(h2);
        o.w = reinterpret_cast<uint32_t&>(h3);
        ((uint4*)g_xh)[e] = o;
    }

    if (e >= E) return;
    int d;
    if (is64) d = (int)((const long long*)ei)[(size_t)E + e];
    else      d = ((const int*)ei)[E + e];
    atomicAdd(&g_deg[d], 1);
}

// ---------------- K1: merged exclusive scan (redundant global prefix) ------
__global__ __launch_bounds__(1024) void k_scan(int n, int E) {
    __shared__ int red[32];
    __shared__ int wpre[32];
    int t = threadIdx.x;
    int lane = t & 31;
    int wid = t >> 5;
    int chunk0 = blockIdx.x << 10;

    int pre = 0;
    for (int i = t; i < chunk0; i += 1024) pre += g_deg[i];
#pragma unroll
    for (int o = 16; o >= 1; o >>= 1) pre += __shfl_xor_sync(0xffffffffu, pre, o);
    if (lane == 0) red[wid] = pre;
    __syncthreads();
    if (t < 32) {
        int v = red[t];
#pragma unroll
        for (int o = 16; o >= 1; o >>= 1) v += __shfl_xor_sync(0xffffffffu, v, o);
        if (t == 0) red[0] = v;
    }
    __syncthreads();
    int prefix = red[0];

    int i = chunk0 + t;
    int d = (i < n) ? g_deg[i] : 0;
    int inc = d;
#pragma unroll
    for (int o = 1; o < 32; o <<= 1) {
        int v = __shfl_up_sync(0xffffffffu, inc, o);
        if (lane >= o) inc += v;
    }
    if (lane == 31) wpre[wid] = inc;
    __syncthreads();
    if (wid == 0) {
        int s = wpre[lane];
        int si = s;
#pragma unroll
        for (int o = 1; o < 32; o <<= 1) {
            int v = __shfl_up_sync(0xffffffffu, si, o);
            if (lane >= o) si += v;
        }
        wpre[lane] = si - s;
    }
    __syncthreads();
    if (i < n) {
        int off = prefix + inc - d + wpre[wid];
        g_off[i] = off;
        g_cur[i] = off;
    }
    if (blockIdx.x == gridDim.x - 1 && t == 0) g_off[n] = E;
}

// ---------------- K2: scatter src into CSR buckets + re-zero g_deg ---------
__global__ void k_scatter(const void* __restrict__ ei, int E, int n) {
    __shared__ unsigned s_or;
    int is64 = detect_i64((const unsigned int*)ei, &s_or);
    int e = blockIdx.x * blockDim.x + threadIdx.x;
    if (e < n) g_deg[e] = 0;
    if (e >= E) return;
    int s, d;
    if (is64) {
        const long long* p = (const long long*)ei;
        s = (int)p[e];
        d = (int)p[(size_t)E + e];
    } else {
        const int* p = (const int*)ei;
        s = p[e];
        d = p[E + e];
    }
    int pos = atomicAdd(&g_cur[d], 1);
    g_csr[pos] = s;
}

// ---------------- fp16 mma helper ------------------------------------------
__device__ __forceinline__ void mma_f16(float* d,
                                        uint32_t a0, uint32_t a1,
                                        uint32_t a2, uint32_t a3,
                                        uint32_t b0, uint32_t b1) {
    asm volatile(
        "mma.sync.aligned.m16n8k16.row.col.f32.f16.f16.f32 "
        "{%0,%1,%2,%3}, {%4,%5,%6,%7}, {%8,%9}, {%0,%1,%2,%3};"
        : "+f"(d[0]), "+f"(d[1]), "+f"(d[2]), "+f"(d[3])
        : "r"(a0), "r"(a1), "r"(a2), "r"(a3), "r"(b0), "r"(b1));
}

// ---------------- K3: fused fp16 gather-max + fp16 MMA + log_softmax -------
// Per block: 64 nodes, 256 threads (8 warps).
//   G: gather-max neighborhoods from g_xh (fp16, 256 B/edge) -> Ash
//   L: stage Wl->Bsh (fp16), acc += agg @ Wl^T via m16n8k16
//   X: stage x(fp16)->Ash + Wr->Bsh, acc += x @ Wr^T
// Even blocks run G,L,X; odd blocks X,G,L (chip-level gather/MMA overlap).
// fp32 gather-max == fp16 gather-max up to one final rounding (monotone cvt).
__global__ __launch_bounds__(256) void k_aggemm(const float* __restrict__ Wl,
                                                const float* __restrict__ bl,
                                                const float* __restrict__ Wr,
                                                float* __restrict__ out, int N) {
    __shared__ uint32_t Ash[64][ROW_W];   // half2 words, k-order
    __shared__ uint32_t Bsh[64][ROW_W];   // col-major weights, half2 words

    int t = threadIdx.x;
    int w = t >> 5;
    int lane = t & 31;
    int nb = blockIdx.x * 64;

    int qid = lane >> 2;     // 0..7
    int tig = lane & 3;      // 0..3
    int wr = (w >> 1) * 16;  // warp node base
    int wn = (w & 1) * 32;   // warp output base

    float acc[4][4];
#pragma unroll
    for (int i = 0; i < 4; i++)
#pragma unroll
        for (int j = 0; j < 4; j++) acc[i][j] = 0.f;

    // ---- phase G: fp16 gather-max into Ash ----
    auto phaseG = [&]() {
        const uint2* xh = (const uint2*)g_xh;    // 4 halves per uint2
        const __half2 NINF2 = __half2half2(__ushort_as_half(0xFC00));
#pragma unroll 1
        for (int r = 0; r < 8; r++) {
            int ln = w * 8 + r;
            int n = nb + ln;
            __half2 m0 = __half2half2(__ushort_as_half(0));
            __half2 m1 = m0;
            if (n < N) {
                int beg = g_off[n];
                int end = g_off[n + 1];
                if (beg < end) {
                    m0 = NINF2; m1 = NINF2;
                    int e = beg;
                    for (; e + 3 < end; e += 4) {
                        int s0 = g_csr[e];
                        int s1 = g_csr[e + 1];
                        int s2 = g_csr[e + 2];
                        int s3 = g_csr[e + 3];
                        uint2 v0 = xh[(size_t)s0 * 32 + lane];
                        uint2 v1 = xh[(size_t)s1 * 32 + lane];
                        uint2 v2 = xh[(size_t)s2 * 32 + lane];
                        uint2 v3 = xh[(size_t)s3 * 32 + lane];
                        m0 = __hmax2(m0, __hmax2(*(__half2*)&v0.x, *(__half2*)&v1.x));
                        m0 = __hmax2(m0, __hmax2(*(__half2*)&v2.x, *(__half2*)&v3.x));
                        m1 = __hmax2(m1, __hmax2(*(__half2*)&v0.y, *(__half2*)&v1.y));
                        m1 = __hmax2(m1, __hmax2(*(__half2*)&v2.y, *(__half2*)&v3.y));
                    }
                    for (; e < end; e++) {
                        int s0 = g_csr[e];
                        uint2 v0 = xh[(size_t)s0 * 32 + lane];
                        m0 = __hmax2(m0, *(__half2*)&v0.x);
                        m1 = __hmax2(m1, *(__half2*)&v0.y);
                    }
                }
            }
            uint2 st;
            st.x = reinterpret_cast<uint32_t&>(m0);
            st.y = reinterpret_cast<uint32_t&>(m1);
            *(uint2*)&Ash[ln][lane * 2] = st;    // k = lane*4 .. lane*4+3
        }
        __syncthreads();
    };

    // ---- stage a weight matrix (fp32 [64][128]) -> Bsh fp16 col-major ----
    auto stageW = [&](const float* __restrict__ W) {
        int c = t >> 2;
        int q = t & 3;
        const float4* Wv = (const float4*)(W + (size_t)c * D_IN + q * 32);
#pragma unroll
        for (int j = 0; j < 4; j++) {
            float4 a = Wv[j * 2];
            float4 b = Wv[j * 2 + 1];
            __half2 h0 = __float22half2_rn(make_float2(a.x, a.y));
            __half2 h1 = __float22half2_rn(make_float2(a.z, a.w));
            __half2 h2 = __float22half2_rn(make_float2(b.x, b.y));
            __half2 h3 = __float22half2_rn(make_float2(b.z, b.w));
            uint4 o;
            o.x = reinterpret_cast<uint32_t&>(h0);
            o.y = reinterpret_cast<uint32_t&>(h1);
            o.z = reinterpret_cast<uint32_t&>(h2);
            o.w = reinterpret_cast<uint32_t&>(h3);
            *(uint4*)&Bsh[c][q * 16 + j * 4] = o;
        }
    };

    // ---- stage x (fp16 from g_xh) -> Ash ----
    auto stageX = [&]() {
        int ln = t >> 2;
        int q = t & 3;
        int n = nb + ln;
        const uint4* src = (const uint4*)(g_xh + (size_t)n * D_IN);
#pragma unroll
        for (int j = 0; j < 4; j++) {
            uint4 v = (n < N) ? src[q * 4 + j] : make_uint4(0, 0, 0, 0);
            *(uint4*)&Ash[ln][q * 16 + j * 4] = v;
        }
    };

    // ---- one full K=128 MMA pass over Ash x Bsh (8 k-steps, 4 n-tiles) ----
    auto mmaAll = [&]() {
#pragma unroll
        for (int ks = 0; ks < 8; ks++) {
            uint32_t a0 = Ash[wr + qid][ks * 8 + tig];
            uint32_t a1 = Ash[wr + qid + 8][ks * 8 + tig];
            uint32_t a2 = Ash[wr + qid][ks * 8 + tig + 4];
            uint32_t a3 = Ash[wr + qid + 8][ks * 8 + tig + 4];
#pragma unroll
            for (int tile = 0; tile < 4; tile++) {
                int col = wn + tile * 8 + qid;
                uint32_t b0 = Bsh[col][ks * 8 + tig];
                uint32_t b1 = Bsh[col][ks * 8 + tig + 4];
                mma_f16(acc[tile], a0, a1, a2, a3, b0, b1);
            }
        }
    };

    auto phaseL = [&]() { stageW(Wl); __syncthreads(); mmaAll(); __syncthreads(); };
    auto phaseX = [&]() { stageX(); stageW(Wr); __syncthreads(); mmaAll(); __syncthreads(); };

    if (blockIdx.x & 1) {
        phaseX();          // MMA first ...
        phaseG();          // ... while even blocks gather
        phaseL();
    } else {
        phaseG();
        phaseL();
        phaseX();
    }

    // ---- epilogue: acc fragments -> smem (+bias), then log_softmax --------
    float (*Os)[OS_PAD] = (float(*)[OS_PAD])Ash;   // overlay (mma consumed)
#pragma unroll
    for (int tile = 0; tile < 4; tile++) {
        int c = wn + tile * 8 + 2 * tig;
        int r0 = wr + qid;
        float b0 = bl[c], b1 = bl[c + 1];
        Os[r0][c]         = acc[tile][0] + b0;
        Os[r0][c + 1]     = acc[tile][1] + b1;
        Os[r0 + 8][c]     = acc[tile][2] + b0;
        Os[r0 + 8][c + 1] = acc[tile][3] + b1;
    }
    __syncthreads();

    // softmax: 4 threads per node row, 16 cols each
    {
        int row = t >> 2;
        int l4 = t & 3;
        float4 v[4];
#pragma unroll
        for (int j = 0; j < 4; j++)
            v[j] = *(const float4*)&Os[row][l4 * 16 + j * 4];

        float m = -CUDART_INF_F;
#pragma unroll
        for (int j = 0; j < 4; j++)
            m = fmaxf(m, fmaxf(fmaxf(v[j].x, v[j].y), fmaxf(v[j].z, v[j].w)));
        m = fmaxf(m, __shfl_xor_sync(0xffffffffu, m, 1));
        m = fmaxf(m, __shfl_xor_sync(0xffffffffu, m, 2));

        float s = 0.f;
#pragma unroll
        for (int j = 0; j < 4; j++)
            s += expf(v[j].x - m) + expf(v[j].y - m) +
                 expf(v[j].z - m) + expf(v[j].w - m);
        s += __shfl_xor_sync(0xffffffffu, s, 1);
        s += __shfl_xor_sync(0xffffffffu, s, 2);
        float lse = m + logf(s);

        int n = nb + row;
        if (n < N) {
#pragma unroll
            for (int j = 0; j < 4; j++) {
                float4 o4 = make_float4(v[j].x - lse, v[j].y - lse,
                                        v[j].z - lse, v[j].w - lse);
                *(float4*)(out + (size_t)n * D_OUT + l4 * 16 + j * 4) = o4;
            }
        }
    }
}

// ---------------- launcher -------------------------------------------------
extern "C" void kernel_launch(void* const* d_in, const int* in_sizes, int n_in,
                              void* d_out, int out_size) {
    const float* x  = (const float*)d_in[0];
    const void*  ei = d_in[1];
    const float* Wl = (const float*)d_in[2];
    const float* bl = (const float*)d_in[3];
    const float* Wr = (const float*)d_in[4];
    float* out = (float*)d_out;

    int N = in_sizes[0] / D_IN;
    int E = in_sizes[1] / 2;
    int n8 = N * (D_IN / 8);            // conversion threads (8 halves each)
    int g0 = (max(E, n8) + 255) / 256;

    // Launch order: ncu profiles OUR index 3 => k_aggemm.
    k_count<<<g0, 256>>>(x, ei, E, n8);                             // 0
    k_scan<<<(N + 1023) / 1024, 1024>>>(N, E);                      // 1
    k_scatter<<<(E + 255) / 256, 256>>>(ei, E, N);                  // 2
    k_aggemm<<<(N + 63) / 64, 256>>>(Wl, bl, Wr, out, N);           // 3
}

// round 12
// speedup vs baseline: 1.8663x; 1.0142x over previous
#include <cuda_runtime.h>
#include <cuda_fp16.h>
#include <math_constants.h>
#include <stdint.h>

// Problem constants (shapes fixed by the reference).
#define MAX_N 100032
#define MAX_E 1600000
#define D_IN  128
#define D_OUT 64

#define ROW_W 68     // half2-words per smem row (64 data + 4 pad); 272 B, 16B-aligned
#define OS_PAD 68    // epilogue float pitch (overlays Ash exactly)

// ---------------- Scratch (static __device__ globals; no runtime allocs) ---
// g_deg is zero at module load; k_scatter re-zeroes it for the NEXT invocation
// (graph replays run the identical sequence, so the invariant holds).
__device__ int    g_deg[MAX_N];
__device__ int    g_off[MAX_N + 1];
__device__ int    g_cur[MAX_N];
__device__ int    g_csr[MAX_E];                 // src indices grouped by dst
__device__ __half g_xh[(size_t)MAX_N * D_IN];   // fp16 copy of x (25.6 MB)

// Per-block inline dtype detect: for int64 (little-endian) edge indices, all
// odd 32-bit words of the first 256 entries are zero. Returns 1 if int64.
__device__ __forceinline__ int detect_i64(const unsigned int* w, unsigned* s_or) {
    if (threadIdx.x == 0) *s_or = 0u;
    __syncthreads();
    if (threadIdx.x < 128) {
        unsigned v = w[2 * threadIdx.x + 1] | w[2 * threadIdx.x + 257];
        if (v) atomicOr(s_or, 1u);
    }
    __syncthreads();
    return (*s_or == 0u) ? 1 : 0;
}

// ---------------- K0: degree histogram + x -> fp16 conversion --------------
__global__ void k_count(const float* __restrict__ x, const void* __restrict__ ei,
                        int E, int n8) {
    __shared__ unsigned s_or;
    int is64 = detect_i64((const unsigned int*)ei, &s_or);
    int e = blockIdx.x * blockDim.x + threadIdx.x;

    if (e < n8) {   // convert 8 floats -> 8 halves (16 B out)
        const float4* xv4 = (const float4*)x;
        float4 a = xv4[(size_t)e * 2];
        float4 b = xv4[(size_t)e * 2 + 1];
        __half2 h0 = __float22half2_rn(make_float2(a.x, a.y));
        __half2 h1 = __float22half2_rn(make_float2(a.z, a.w));
        __half2 h2 = __float22half2_rn(make_float2(b.x, b.y));
        __half2 h3 = __float22half2_rn(make_float2(b.z, b.w));
        uint4 o;
        o.x = reinterpret_cast<uint32_t&>(h0);
        o.y = reinterpret_cast<uint32_t&>(h1);
        o.z = reinterpret_cast<uint32_t&>(h2);
        o.w = reinterpret_cast<uint32_t&>(h3);
        ((uint4*)g_xh)[e] = o;
    }

    if (e >= E) return;
    int d;
    if (is64) d = (int)((const long long*)ei)[(size_t)E + e];
    else      d = ((const int*)ei)[E + e];
    atomicAdd(&g_deg[d], 1);
}

// ---------------- K1: merged exclusive scan (redundant global prefix) ------
__global__ __launch_bounds__(1024) void k_scan(int n, int E) {
    __shared__ int red[32];
    __shared__ int wpre[32];
    int t = threadIdx.x;
    int lane = t & 31;
    int wid = t >> 5;
    int chunk0 = blockIdx.x << 10;

    int pre = 0;
    for (int i = t; i < chunk0; i += 1024) pre += g_deg[i];
#pragma unroll
    for (int o = 16; o >= 1; o >>= 1) pre += __shfl_xor_sync(0xffffffffu, pre, o);
    if (lane == 0) red[wid] = pre;
    __syncthreads();
    if (t < 32) {
        int v = red[t];
#pragma unroll
        for (int o = 16; o >= 1; o >>= 1) v += __shfl_xor_sync(0xffffffffu, v, o);
        if (t == 0) red[0] = v;
    }
    __syncthreads();
    int prefix = red[0];

    int i = chunk0 + t;
    int d = (i < n) ? g_deg[i] : 0;
    int inc = d;
#pragma unroll
    for (int o = 1; o < 32; o <<= 1) {
        int v = __shfl_up_sync(0xffffffffu, inc, o);
        if (lane >= o) inc += v;
    }
    if (lane == 31) wpre[wid] = inc;
    __syncthreads();
    if (wid == 0) {
        int s = wpre[lane];
        int si = s;
#pragma unroll
        for (int o = 1; o < 32; o <<= 1) {
            int v = __shfl_up_sync(0xffffffffu, si, o);
            if (lane >= o) si += v;
        }
        wpre[lane] = si - s;
    }
    __syncthreads();
    if (i < n) {
        int off = prefix + inc - d + wpre[wid];
        g_off[i] = off;
        g_cur[i] = off;
    }
    if (blockIdx.x == gridDim.x - 1 && t == 0) g_off[n] = E;
}

// ---------------- K2: scatter src into CSR buckets + re-zero g_deg ---------
__global__ void k_scatter(const void* __restrict__ ei, int E, int n) {
    __shared__ unsigned s_or;
    int is64 = detect_i64((const unsigned int*)ei, &s_or);
    int e = blockIdx.x * blockDim.x + threadIdx.x;
    if (e < n) g_deg[e] = 0;
    if (e >= E) return;
    int s, d;
    if (is64) {
        const long long* p = (const long long*)ei;
        s = (int)p[e];
        d = (int)p[(size_t)E + e];
    } else {
        const int* p = (const int*)ei;
        s = p[e];
        d = p[E + e];
    }
    int pos = atomicAdd(&g_cur[d], 1);
    g_csr[pos] = s;
}

// ---------------- fp16 mma helper ------------------------------------------
__device__ __forceinline__ void mma_f16(float* d,
                                        uint32_t a0, uint32_t a1,
                                        uint32_t a2, uint32_t a3,
                                        uint32_t b0, uint32_t b1) {
    asm volatile(
        "mma.sync.aligned.m16n8k16.row.col.f32.f16.f16.f32 "
        "{%0,%1,%2,%3}, {%4,%5,%6,%7}, {%8,%9}, {%0,%1,%2,%3};"
        : "+f"(d[0]), "+f"(d[1]), "+f"(d[2]), "+f"(d[3])
        : "r"(a0), "r"(a1), "r"(a2), "r"(a3), "r"(b0), "r"(b1));
}

__device__ __forceinline__ __half2 hmax2u(__half2 a, uint32_t ub) {
    return __hmax2(a, *(__half2*)&ub);
}

// ---------------- K3: fused fp16 gather-max + fp16 MMA + log_softmax -------
// Per block: 64 nodes, 256 threads (8 warps).
//   G: gather-max from g_xh. Wide form: lanes 0-15 cover edge e's 256B row
//      (uint4/lane), lanes 16-31 cover edge e+1 -> one LDG.128 warp-op loads
//      2 edges; main loop keeps 8 edges (4 loads) in flight. Sides merge via
//      shfl_xor(16) at node end; lanes 0-15 store the row (uint4).
//   L: stage Wl->Bsh (fp16), acc += agg @ Wl^T via m16n8k16
//   X: stage x(fp16)->Ash + Wr->Bsh, acc += x @ Wr^T
// Even blocks run G,L,X; odd blocks X,G,L (chip-level gather/MMA overlap).
__global__ __launch_bounds__(256) void k_aggemm(const float* __restrict__ Wl,
                                                const float* __restrict__ bl,
                                                const float* __restrict__ Wr,
                                                float* __restrict__ out, int N) {
    __shared__ uint32_t Ash[64][ROW_W];   // half2 words, k-order
    __shared__ uint32_t Bsh[64][ROW_W];   // col-major weights, half2 words

    int t = threadIdx.x;
    int w = t >> 5;
    int lane = t & 31;
    int nb = blockIdx.x * 64;

    int qid = lane >> 2;     // 0..7
    int tig = lane & 3;      // 0..3
    int wr = (w >> 1) * 16;  // warp node base
    int wn = (w & 1) * 32;   // warp output base

    float acc[4][4];
#pragma unroll
    for (int i = 0; i < 4; i++)
#pragma unroll
        for (int j = 0; j < 4; j++) acc[i][j] = 0.f;

    // ---- phase G: wide fp16 gather-max into Ash ----
    auto phaseG = [&]() {
        const uint4* xh4 = (const uint4*)g_xh;   // 8 halves per uint4; row = 16
        int side = lane >> 4;    // 0: even edge of pair, 1: odd edge
        int h = lane & 15;       // uint4 index within the 256B row
        const __half2 NINF2 = __half2half2(__ushort_as_half(0xFC00));
#pragma unroll 1
        for (int r = 0; r < 8; r++) {
            int ln = w * 8 + r;
            int n = nb + ln;
            __half2 a0 = __half2half2(__ushort_as_half(0));
            __half2 a1 = a0, a2 = a0, a3 = a0;
            if (n < N) {
                int beg = g_off[n];
                int end = g_off[n + 1];
                if (beg < end) {
                    a0 = NINF2; a1 = NINF2; a2 = NINF2; a3 = NINF2;
                    int e = beg;
                    for (; e + 7 < end; e += 8) {       // 8 edges, 4 LDG.128
                        int i0 = g_csr[e + side];
                        int i1 = g_csr[e + 2 + side];
                        int i2 = g_csr[e + 4 + side];
                        int i3 = g_csr[e + 6 + side];
                        uint4 v0 = xh4[(size_t)i0 * 16 + h];
                        uint4 v1 = xh4[(size_t)i1 * 16 + h];
                        uint4 v2 = xh4[(size_t)i2 * 16 + h];
                        uint4 v3 = xh4[(size_t)i3 * 16 + h];
                        a0 = __hmax2(__hmax2(hmax2u(a0, v0.x), *(__half2*)&v1.x),
                                     __hmax2(*(__half2*)&v2.x, *(__half2*)&v3.x));
                        a1 = __hmax2(__hmax2(hmax2u(a1, v0.y), *(__half2*)&v1.y),
                                     __hmax2(*(__half2*)&v2.y, *(__half2*)&v3.y));
                        a2 = __hmax2(__hmax2(hmax2u(a2, v0.z), *(__half2*)&v1.z),
                                     __hmax2(*(__half2*)&v2.z, *(__half2*)&v3.z));
                        a3 = __hmax2(__hmax2(hmax2u(a3, v0.w), *(__half2*)&v1.w),
                                     __hmax2(*(__half2*)&v2.w, *(__half2*)&v3.w));
                    }
                    for (; e + 1 < end; e += 2) {       // pairs
                        int i0 = g_csr[e + side];
                        uint4 v0 = xh4[(size_t)i0 * 16 + h];
                        a0 = hmax2u(a0, v0.x);
                        a1 = hmax2u(a1, v0.y);
                        a2 = hmax2u(a2, v0.z);
                        a3 = hmax2u(a3, v0.w);
                    }
                    if (e < end && side == 0) {         // odd tail
                        int i0 = g_csr[e];
                        uint4 v0 = xh4[(size_t)i0 * 16 + h];
                        a0 = hmax2u(a0, v0.x);
                        a1 = hmax2u(a1, v0.y);
                        a2 = hmax2u(a2, v0.z);
                        a3 = hmax2u(a3, v0.w);
                    }
                }
            }
            // merge sides (lane i <-> i+16), then lanes 0-15 hold the row
            a0 = hmax2u(a0, __shfl_xor_sync(0xffffffffu,
                              reinterpret_cast<uint32_t&>(a0), 16));
            a1 = hmax2u(a1, __shfl_xor_sync(0xffffffffu,
                              reinterpret_cast<uint32_t&>(a1), 16));
            a2 = hmax2u(a2, __shfl_xor_sync(0xffffffffu,
                              reinterpret_cast<uint32_t&>(a2), 16));
            a3 = hmax2u(a3, __shfl_xor_sync(0xffffffffu,
                              reinterpret_cast<uint32_t&>(a3), 16));
            if (side == 0) {
                uint4 st;
                st.x = reinterpret_cast<uint32_t&>(a0);
                st.y = reinterpret_cast<uint32_t&>(a1);
                st.z = reinterpret_cast<uint32_t&>(a2);
                st.w = reinterpret_cast<uint32_t&>(a3);
                *(uint4*)&Ash[ln][h * 4] = st;   // halves k = 8h..8h+7
            }
        }
        __syncthreads();
    };

    // ---- stage a weight matrix (fp32 [64][128]) -> Bsh fp16 col-major ----
    auto stageW = [&](const float* __restrict__ W) {
        int c = t >> 2;
        int q = t & 3;
        const float4* Wv = (const float4*)(W + (size_t)c * D_IN + q * 32);
#pragma unroll
        for (int j = 0; j < 4; j++) {
            float4 a = Wv[j * 2];
            float4 b = Wv[j * 2 + 1];
            __half2 h0 = __float22half2_rn(make_float2(a.x, a.y));
            __half2 h1 = __float22half2_rn(make_float2(a.z, a.w));
            __half2 h2 = __float22half2_rn(make_float2(b.x, b.y));
            __half2 h3 = __float22half2_rn(make_float2(b.z, b.w));
            uint4 o;
            o.x = reinterpret_cast<uint32_t&>(h0);
            o.y = reinterpret_cast<uint32_t&>(h1);
            o.z = reinterpret_cast<uint32_t&>(h2);
            o.w = reinterpret_cast<uint32_t&>(h3);
            *(uint4*)&Bsh[c][q * 16 + j * 4] = o;
        }
    };

    // ---- stage x (fp16 from g_xh) -> Ash ----
    auto stageX = [&]() {
        int ln = t >> 2;
        int q = t & 3;
        int n = nb + ln;
        const uint4* src = (const uint4*)(g_xh + (size_t)n * D_IN);
#pragma unroll
        for (int j = 0; j < 4; j++) {
            uint4 v = (n < N) ? src[q * 4 + j] : make_uint4(0, 0, 0, 0);
            *(uint4*)&Ash[ln][q * 16 + j * 4] = v;
        }
    };

    // ---- one full K=128 MMA pass over Ash x Bsh (8 k-steps, 4 n-tiles) ----
    auto mmaAll = [&]() {
#pragma unroll
        for (int ks = 0; ks < 8; ks++) {
            uint32_t a0 = Ash[wr + qid][ks * 8 + tig];
            uint32_t a1 = Ash[wr + qid + 8][ks * 8 + tig];
            uint32_t a2 = Ash[wr + qid][ks * 8 + tig + 4];
            uint32_t a3 = Ash[wr + qid + 8][ks * 8 + tig + 4];
#pragma unroll
            for (int tile = 0; tile < 4; tile++) {
                int col = wn + tile * 8 + qid;
                uint32_t b0 = Bsh[col][ks * 8 + tig];
                uint32_t b1 = Bsh[col][ks * 8 + tig + 4];
                mma_f16(acc[tile], a0, a1, a2, a3, b0, b1);
            }
        }
    };

    auto phaseL = [&]() { stageW(Wl); __syncthreads(); mmaAll(); __syncthreads(); };
    auto phaseX = [&]() { stageX(); stageW(Wr); __syncthreads(); mmaAll(); __syncthreads(); };

    if (blockIdx.x & 1) {
        phaseX();          // MMA first ...
        phaseG();          // ... while even blocks gather
        phaseL();
    } else {
        phaseG();
        phaseL();
        phaseX();
    }

    // ---- epilogue: acc fragments -> smem (+bias), then log_softmax --------
    float (*Os)[OS_PAD] = (float(*)[OS_PAD])Ash;   // overlay (mma consumed)
#pragma unroll
    for (int tile = 0; tile < 4; tile++) {
        int c = wn + tile * 8 + 2 * tig;
        int r0 = wr + qid;
        float b0 = bl[c], b1 = bl[c + 1];
        Os[r0][c]         = acc[tile][0] + b0;
        Os[r0][c + 1]     = acc[tile][1] + b1;
        Os[r0 + 8][c]     = acc[tile][2] + b0;
        Os[r0 + 8][c + 1] = acc[tile][3] + b1;
    }
    __syncthreads();

    // softmax: 4 threads per node row, 16 cols each
    {
        int row = t >> 2;
        int l4 = t & 3;
        float4 v[4];
#pragma unroll
        for (int j = 0; j < 4; j++)
            v[j] = *(const float4*)&Os[row][l4 * 16 + j * 4];

        float m = -CUDART_INF_F;
#pragma unroll
        for (int j = 0; j < 4; j++)
            m = fmaxf(m, fmaxf(fmaxf(v[j].x, v[j].y), fmaxf(v[j].z, v[j].w)));
        m = fmaxf(m, __shfl_xor_sync(0xffffffffu, m, 1));
        m = fmaxf(m, __shfl_xor_sync(0xffffffffu, m, 2));

        float s = 0.f;
#pragma unroll
        for (int j = 0; j < 4; j++)
            s += expf(v[j].x - m) + expf(v[j].y - m) +
                 expf(v[j].z - m) + expf(v[j].w - m);
        s += __shfl_xor_sync(0xffffffffu, s, 1);
        s += __shfl_xor_sync(0xffffffffu, s, 2);
        float lse = m + logf(s);

        int n = nb + row;
        if (n < N) {
#pragma unroll
            for (int j = 0; j < 4; j++) {
                float4 o4 = make_float4(v[j].x - lse, v[j].y - lse,
                                        v[j].z - lse, v[j].w - lse);
                *(float4*)(out + (size_t)n * D_OUT + l4 * 16 + j * 4) = o4;
            }
        }
    }
}

// ---------------- launcher -------------------------------------------------
extern "C" void kernel_launch(void* const* d_in, const int* in_sizes, int n_in,
                              void* d_out, int out_size) {
    const float* x  = (const float*)d_in[0];
    const void*  ei = d_in[1];
    const float* Wl = (const float*)d_in[2];
    const float* bl = (const float*)d_in[3];
    const float* Wr = (const float*)d_in[4];
    float* out = (float*)d_out;

    int N = in_sizes[0] / D_IN;
    int E = in_sizes[1] / 2;
    int n8 = N * (D_IN / 8);            // conversion threads (8 halves each)
    int g0 = (max(E, n8) + 255) / 256;

    // Launch order: ncu profiles OUR index 3 => k_aggemm.
    k_count<<<g0, 256>>>(x, ei, E, n8);                             // 0
    k_scan<<<(N + 1023) / 1024, 1024>>>(N, E);                      // 1
    k_scatter<<<(E + 255) / 256, 256>>>(ei, E, N);                  // 2
    k_aggemm<<<(N + 63) / 64, 256>>>(Wl, bl, Wr, out, N);           // 3
}

// round 13
// speedup vs baseline: 1.9090x; 1.0229x over previous
#include <cuda_runtime.h>
#include <cuda_fp16.h>
#include <math_constants.h>
#include <stdint.h>

// Problem constants (shapes fixed by the reference).
#define MAX_N 100032
#define MAX_E 1600000
#define D_IN  128
#define D_OUT 64

#define ROW_W 68     // half2-words per smem row (64 data + 4 pad); 272 B, 16B-aligned
#define OS_PAD 68    // epilogue float pitch (overlays Ash exactly)

// ---------------- Scratch (static __device__ globals; no runtime allocs) ---
// g_deg is zero at module load; k_scatter re-zeroes it for the NEXT invocation
// (graph replays run the identical sequence, so the invariant holds).
__device__ int    g_deg[MAX_N];
__device__ int    g_off[MAX_N + 1];
__device__ int    g_cur[MAX_N];
__device__ int    g_csr[MAX_E];                 // src indices grouped by dst
__device__ __align__(256) __half g_xh[(size_t)MAX_N * D_IN];   // fp16 x copy

// Per-block inline dtype detect: for int64 (little-endian) edge indices, all
// odd 32-bit words of the first 256 entries are zero. Returns 1 if int64.
__device__ __forceinline__ int detect_i64(const unsigned int* w, unsigned* s_or) {
    if (threadIdx.x == 0) *s_or = 0u;
    __syncthreads();
    if (threadIdx.x < 128) {
        unsigned v = w[2 * threadIdx.x + 1] | w[2 * threadIdx.x + 257];
        if (v) atomicOr(s_or, 1u);
    }
    __syncthreads();
    return (*s_or == 0u) ? 1 : 0;
}

// ---------------- K0: degree histogram + x -> fp16 conversion --------------
__global__ void k_count(const float* __restrict__ x, const void* __restrict__ ei,
                        int E, int n8) {
    __shared__ unsigned s_or;
    int is64 = detect_i64((const unsigned int*)ei, &s_or);
    int e = blockIdx.x * blockDim.x + threadIdx.x;

    if (e < n8) {   // convert 8 floats -> 8 halves (16 B out)
        const float4* xv4 = (const float4*)x;
        float4 a = xv4[(size_t)e * 2];
        float4 b = xv4[(size_t)e * 2 + 1];
        __half2 h0 = __float22half2_rn(make_float2(a.x, a.y));
        __half2 h1 = __float22half2_rn(make_float2(a.z, a.w));
        __half2 h2 = __float22half2_rn(make_float2(b.x, b.y));
        __half2 h3 = __float22half2_rn(make_float2(b.z, b.w));
        uint4 o;
        o.x = reinterpret_cast<uint32_t&>(h0);
        o.y = reinterpret_cast<uint32_t&>(h1);
        o.z = reinterpret_cast<uint32_t&>(h2);
        o.w = reinterpret_cast<uint32_t&>(h3);
        ((uint4*)g_xh)[e] = o;
    }

    if (e >= E) return;
    int d;
    if (is64) d = (int)((const long long*)ei)[(size_t)E + e];
    else      d = ((const int*)ei)[E + e];
    atomicAdd(&g_deg[d], 1);
}

// ---------------- K1: merged exclusive scan (redundant global prefix) ------
__global__ __launch_bounds__(1024) void k_scan(int n, int E) {
    __shared__ int red[32];
    __shared__ int wpre[32];
    int t = threadIdx.x;
    int lane = t & 31;
    int wid = t >> 5;
    int chunk0 = blockIdx.x << 10;

    int pre = 0;
    for (int i = t; i < chunk0; i += 1024) pre += g_deg[i];
#pragma unroll
    for (int o = 16; o >= 1; o >>= 1) pre += __shfl_xor_sync(0xffffffffu, pre, o);
    if (lane == 0) red[wid] = pre;
    __syncthreads();
    if (t < 32) {
        int v = red[t];
#pragma unroll
        for (int o = 16; o >= 1; o >>= 1) v += __shfl_xor_sync(0xffffffffu, v, o);
        if (t == 0) red[0] = v;
    }
    __syncthreads();
    int prefix = red[0];

    int i = chunk0 + t;
    int d = (i < n) ? g_deg[i] : 0;
    int inc = d;
#pragma unroll
    for (int o = 1; o < 32; o <<= 1) {
        int v = __shfl_up_sync(0xffffffffu, inc, o);
        if (lane >= o) inc += v;
    }
    if (lane == 31) wpre[wid] = inc;
    __syncthreads();
    if (wid == 0) {
        int s = wpre[lane];
        int si = s;
#pragma unroll
        for (int o = 1; o < 32; o <<= 1) {
            int v = __shfl_up_sync(0xffffffffu, si, o);
            if (lane >= o) si += v;
        }
        wpre[lane] = si - s;
    }
    __syncthreads();
    if (i < n) {
        int off = prefix + inc - d + wpre[wid];
        g_off[i] = off;
        g_cur[i] = off;
    }
    if (blockIdx.x == gridDim.x - 1 && t == 0) g_off[n] = E;
}

// ---------------- K2: scatter src into CSR buckets + re-zero g_deg ---------
__global__ void k_scatter(const void* __restrict__ ei, int E, int n) {
    __shared__ unsigned s_or;
    int is64 = detect_i64((const unsigned int*)ei, &s_or);
    int e = blockIdx.x * blockDim.x + threadIdx.x;
    if (e < n) g_deg[e] = 0;
    if (e >= E) return;
    int s, d;
    if (is64) {
        const long long* p = (const long long*)ei;
        s = (int)p[e];
        d = (int)p[(size_t)E + e];
    } else {
        const int* p = (const int*)ei;
        s = p[e];
        d = p[E + e];
    }
    int pos = atomicAdd(&g_cur[d], 1);
    g_csr[pos] = s;
}

// ---------------- helpers ---------------------------------------------------
__device__ __forceinline__ void mma_f16(float* d,
                                        uint32_t a0, uint32_t a1,
                                        uint32_t a2, uint32_t a3,
                                        uint32_t b0, uint32_t b1) {
    asm volatile(
        "mma.sync.aligned.m16n8k16.row.col.f32.f16.f16.f32 "
        "{%0,%1,%2,%3}, {%4,%5,%6,%7}, {%8,%9}, {%0,%1,%2,%3};"
        : "+f"(d[0]), "+f"(d[1]), "+f"(d[2]), "+f"(d[3])
        : "r"(a0), "r"(a1), "r"(a2), "r"(a3), "r"(b0), "r"(b1));
}

__device__ __forceinline__ __half2 hmax2u(__half2 a, uint32_t ub) {
    return __hmax2(a, *(__half2*)&ub);
}

__device__ __forceinline__ void cp16(uint32_t smem_addr, const void* gptr) {
    asm volatile("cp.async.cg.shared.global [%0], [%1], 16;"
                 :: "r"(smem_addr), "l"(gptr) : "memory");
}

// ---------------- K3: fused cp.async gather-max + fp16 MMA + log_softmax ---
// Per block: 64 nodes, 256 threads (8 warps).
//   G: per warp, neighbor rows staged global->smem via cp.async.cg (L1
//      bypass, no register landing) in 4-edge (1 KB) double-buffered groups;
//      reduce with hmax2 from smem. Staging OVERLAYS Bsh (phaseG never
//      coexists with Bsh weight use). Side merge via shfl_xor(16).
//   L: stage Wl->Bsh (fp16), acc += agg @ Wl^T via m16n8k16
//   X: stage x(fp16)->Ash + Wr->Bsh, acc += x @ Wr^T
// Even blocks run G,L,X; odd blocks X,G,L (chip-level gather/MMA overlap).
__global__ __launch_bounds__(256) void k_aggemm(const float* __restrict__ Wl,
                                                const float* __restrict__ bl,
                                                const float* __restrict__ Wr,
                                                float* __restrict__ out, int N) {
    __shared__ uint32_t Ash[64][ROW_W];   // half2 words, k-order
    __shared__ uint32_t Bsh[64][ROW_W];   // col-major weights / gather staging

    int t = threadIdx.x;
    int w = t >> 5;
    int lane = t & 31;
    int nb = blockIdx.x * 64;

    int qid = lane >> 2;     // 0..7
    int tig = lane & 3;      // 0..3
    int wr = (w >> 1) * 16;  // warp node base
    int wn = (w & 1) * 32;   // warp output base

    float acc[4][4];
#pragma unroll
    for (int i = 0; i < 4; i++)
#pragma unroll
        for (int j = 0; j < 4; j++) acc[i][j] = 0.f;

    // ---- phase G: cp.async-staged fp16 gather-max into Ash ----
    auto phaseG = [&]() {
        const char* xb = (const char*)g_xh;          // 256 B per node row
        char* sbase = (char*)&Bsh[0][0] + w * 2048;  // per-warp 2x1KB staging
        uint32_t sbase_u = (uint32_t)__cvta_generic_to_shared(sbase);
        int side = lane >> 4;    // which row-pair of the 4-row group
        int off = lane & 15;     // 16B chunk within a 256B row
        int coff = off * 16;
        const __half2 NINF2 = __half2half2(__ushort_as_half(0xFC00));
#pragma unroll 1
        for (int r = 0; r < 8; r++) {
            int ln = w * 8 + r;
            int n = nb + ln;
            __half2 a0 = __half2half2(__ushort_as_half(0));
            __half2 a1 = a0, a2 = a0, a3 = a0;
            if (n < N) {
                int beg = g_off[n];
                int end = g_off[n + 1];
                if (beg < end) {
                    a0 = NINF2; a1 = NINF2; a2 = NINF2; a3 = NINF2;
                    int G = (end - beg + 3) >> 2;    // 4-edge groups (padded)
                    // rows: side (edge g4+side), side+2 (edge g4+2+side)
                    auto issue = [&](int g) {
                        int e0 = beg + g * 4;
                        int i0 = g_csr[min(e0 + side, end - 1)];
                        int i1 = g_csr[min(e0 + 2 + side, end - 1)];
                        uint32_t d = sbase_u + ((g & 1) << 10);
                        cp16(d + (side << 8) + coff, xb + ((size_t)i0 << 8) + coff);
                        cp16(d + ((side + 2) << 8) + coff, xb + ((size_t)i1 << 8) + coff);
                        asm volatile("cp.async.commit_group;" ::: "memory");
                    };
                    int pending = 1;
                    issue(0);
                    if (G > 1) { issue(1); pending = 2; }
#pragma unroll 1
                    for (int g = 0; g < G; g++) {
                        if (pending == 2)
                            asm volatile("cp.async.wait_group 1;" ::: "memory");
                        else
                            asm volatile("cp.async.wait_group 0;" ::: "memory");
                        pending--;
                        const char* sb = sbase + ((g & 1) << 10);
                        uint4 v0 = *(const uint4*)(sb + (side << 8) + coff);
                        uint4 v1 = *(const uint4*)(sb + ((side + 2) << 8) + coff);
                        if (g + 2 < G) { issue(g + 2); pending++; }
                        a0 = hmax2u(hmax2u(a0, v0.x), v1.x);
                        a1 = hmax2u(hmax2u(a1, v0.y), v1.y);
                        a2 = hmax2u(hmax2u(a2, v0.z), v1.z);
                        a3 = hmax2u(hmax2u(a3, v0.w), v1.w);
                    }
                }
            }
            // merge sides (lane i <-> i+16); lanes 0-15 hold the row
            a0 = hmax2u(a0, __shfl_xor_sync(0xffffffffu,
                              reinterpret_cast<uint32_t&>(a0), 16));
            a1 = hmax2u(a1, __shfl_xor_sync(0xffffffffu,
                              reinterpret_cast<uint32_t&>(a1), 16));
            a2 = hmax2u(a2, __shfl_xor_sync(0xffffffffu,
                              reinterpret_cast<uint32_t&>(a2), 16));
            a3 = hmax2u(a3, __shfl_xor_sync(0xffffffffu,
                              reinterpret_cast<uint32_t&>(a3), 16));
            if (side == 0) {
                uint4 st;
                st.x = reinterpret_cast<uint32_t&>(a0);
                st.y = reinterpret_cast<uint32_t&>(a1);
                st.z = reinterpret_cast<uint32_t&>(a2);
                st.w = reinterpret_cast<uint32_t&>(a3);
                *(uint4*)&Ash[ln][off * 4] = st;   // halves k = 8*off..8*off+7
            }
        }
        __syncthreads();
    };

    // ---- stage a weight matrix (fp32 [64][128]) -> Bsh fp16 col-major ----
    auto stageW = [&](const float* __restrict__ W) {
        int c = t >> 2;
        int q = t & 3;
        const float4* Wv = (const float4*)(W + (size_t)c * D_IN + q * 32);
#pragma unroll
        for (int j = 0; j < 4; j++) {
            float4 a = Wv[j * 2];
            float4 b = Wv[j * 2 + 1];
            __half2 h0 = __float22half2_rn(make_float2(a.x, a.y));
            __half2 h1 = __float22half2_rn(make_float2(a.z, a.w));
            __half2 h2 = __float22half2_rn(make_float2(b.x, b.y));
            __half2 h3 = __float22half2_rn(make_float2(b.z, b.w));
            uint4 o;
            o.x = reinterpret_cast<uint32_t&>(h0);
            o.y = reinterpret_cast<uint32_t&>(h1);
            o.z = reinterpret_cast<uint32_t&>(h2);
            o.w = reinterpret_cast<uint32_t&>(h3);
            *(uint4*)&Bsh[c][q * 16 + j * 4] = o;
        }
    };

    // ---- stage x (fp16 from g_xh) -> Ash ----
    auto stageX = [&]() {
        int ln = t >> 2;
        int q = t & 3;
        int n = nb + ln;
        const uint4* src = (const uint4*)(g_xh + (size_t)n * D_IN);
#pragma unroll
        for (int j = 0; j < 4; j++) {
            uint4 v = (n < N) ? src[q * 4 + j] : make_uint4(0, 0, 0, 0);
            *(uint4*)&Ash[ln][q * 16 + j * 4] = v;
        }
    };

    // ---- one full K=128 MMA pass over Ash x Bsh (8 k-steps, 4 n-tiles) ----
    auto mmaAll = [&]() {
#pragma unroll
        for (int ks = 0; ks < 8; ks++) {
            uint32_t a0 = Ash[wr + qid][ks * 8 + tig];
            uint32_t a1 = Ash[wr + qid + 8][ks * 8 + tig];
            uint32_t a2 = Ash[wr + qid][ks * 8 + tig + 4];
            uint32_t a3 = Ash[wr + qid + 8][ks * 8 + tig + 4];
#pragma unroll
            for (int tile = 0; tile < 4; tile++) {
                int col = wn + tile * 8 + qid;
                uint32_t b0 = Bsh[col][ks * 8 + tig];
                uint32_t b1 = Bsh[col][ks * 8 + tig + 4];
                mma_f16(acc[tile], a0, a1, a2, a3, b0, b1);
            }
        }
    };

    auto phaseL = [&]() { stageW(Wl); __syncthreads(); mmaAll(); __syncthreads(); };
    auto phaseX = [&]() { stageX(); stageW(Wr); __syncthreads(); mmaAll(); __syncthreads(); };

    if (blockIdx.x & 1) {
        phaseX();          // MMA first ...
        phaseG();          // ... while even blocks gather
        phaseL();
    } else {
        phaseG();
        phaseL();
        phaseX();
    }

    // ---- epilogue: acc fragments -> smem (+bias), then log_softmax --------
    float (*Os)[OS_PAD] = (float(*)[OS_PAD])Ash;   // overlay (mma consumed)
#pragma unroll
    for (int tile = 0; tile < 4; tile++) {
        int c = wn + tile * 8 + 2 * tig;
        int r0 = wr + qid;
        float b0 = bl[c], b1 = bl[c + 1];
        Os[r0][c]         = acc[tile][0] + b0;
        Os[r0][c + 1]     = acc[tile][1] + b1;
        Os[r0 + 8][c]     = acc[tile][2] + b0;
        Os[r0 + 8][c + 1] = acc[tile][3] + b1;
    }
    __syncthreads();

    // softmax: 4 threads per node row, 16 cols each
    {
        int row = t >> 2;
        int l4 = t & 3;
        float4 v[4];
#pragma unroll
        for (int j = 0; j < 4; j++)
            v[j] = *(const float4*)&Os[row][l4 * 16 + j * 4];

        float m = -CUDART_INF_F;
#pragma unroll
        for (int j = 0; j < 4; j++)
            m = fmaxf(m, fmaxf(fmaxf(v[j].x, v[j].y), fmaxf(v[j].z, v[j].w)));
        m = fmaxf(m, __shfl_xor_sync(0xffffffffu, m, 1));
        m = fmaxf(m, __shfl_xor_sync(0xffffffffu, m, 2));

        float s = 0.f;
#pragma unroll
        for (int j = 0; j < 4; j++)
            s += expf(v[j].x - m) + expf(v[j].y - m) +
                 expf(v[j].z - m) + expf(v[j].w - m);
        s += __shfl_xor_sync(0xffffffffu, s, 1);
        s += __shfl_xor_sync(0xffffffffu, s, 2);
        float lse = m + logf(s);

        int n = nb + row;
        if (n < N) {
#pragma unroll
            for (int j = 0; j < 4; j++) {
                float4 o4 = make_float4(v[j].x - lse, v[j].y - lse,
                                        v[j].z - lse, v[j].w - lse);
                *(float4*)(out + (size_t)n * D_OUT + l4 * 16 + j * 4) = o4;
            }
        }
    }
}

// ---------------- launcher -------------------------------------------------
extern "C" void kernel_launch(void* const* d_in, const int* in_sizes, int n_in,
                              void* d_out, int out_size) {
    const float* x  = (const float*)d_in[0];
    const void*  ei = d_in[1];
    const float* Wl = (const float*)d_in[2];
    const float* bl = (const float*)d_in[3];
    const float* Wr = (const float*)d_in[4];
    float* out = (float*)d_out;

    int N = in_sizes[0] / D_IN;
    int E = in_sizes[1] / 2;
    int n8 = N * (D_IN / 8);            // conversion threads (8 halves each)
    int g0 = (max(E, n8) + 255) / 256;

    // Launch order: ncu profiles OUR index 3 => k_aggemm.
    k_count<<<g0, 256>>>(x, ei, E, n8);                             // 0
    k_scan<<<(N + 1023) / 1024, 1024>>>(N, E);                      // 1
    k_scatter<<<(E + 255) / 256, 256>>>(ei, E, N);                  // 2
    k_aggemm<<<(N + 63) / 64, 256>>>(Wl, bl, Wr, out, N);           // 3
}